// round 1
// baseline (speedup 1.0000x reference)
#include <cuda_runtime.h>

#define NB 8
#define NP 2048
#define KNN 20
#define CF 323
#define NEG 0.2f

// ---------------- scratch (device globals; no allocations) ----------------
__device__ float g_feat[NB*NP*CF];      // [b][n][c] : pts|f1|f2|f3|f4
__device__ float g_featT[NB*CF*NP];     // [b][c][n]
__device__ float g_sq[NB*NP];
__device__ int   g_knn[NB*NP*KNN];
__device__ float g_A[NB*NP*128];        // feat @ Wd^T
__device__ float g_B2[NB*NP*128];       // feat @ Wc^T
__device__ float g_W5T[323*1024];
__device__ unsigned int g_gmax[NB*1024];
__device__ float g_gfeat[NB*1024];
__device__ float g_h1[NB*512];
__device__ float g_h2[NB*256];

__device__ __forceinline__ unsigned enc_f(float f){
    unsigned u = __float_as_uint(f);
    return (u & 0x80000000u) ? ~u : (u | 0x80000000u);
}
__device__ __forceinline__ float dec_f(unsigned u){
    return (u & 0x80000000u) ? __uint_as_float(u ^ 0x80000000u) : __uint_as_float(~u);
}
__device__ __forceinline__ float lrelu(float z){ return z > 0.f ? z : NEG*z; }

// ---------------- init: transpose x into feat/featT, reset maxpool --------
__global__ void k_init(const float* __restrict__ x){
    int idx = blockIdx.x*256 + threadIdx.x;       // NB*NP threads
    int b = idx >> 11, n = idx & (NP-1);
    #pragma unroll
    for (int c = 0; c < 3; c++){
        float v = x[(b*3 + c)*NP + n];
        g_feat[idx*CF + c] = v;
        g_featT[(b*CF + c)*NP + n] = v;
    }
}

__global__ void k_initmax(){
    int idx = blockIdx.x*256 + threadIdx.x;
    if (idx < NB*1024) g_gmax[idx] = 0u;
}

// ---------------- squared norms over the C-prefix -------------------------
__global__ void k_sq(int cin){
    int idx = blockIdx.x*256 + threadIdx.x;       // NB*NP threads
    int b = idx >> 11, n = idx & (NP-1);
    const float* fT = g_featT + (b*CF)*NP + n;
    float s = 0.f;
    for (int c = 0; c < cin; c++){ float v = fT[c*NP]; s = fmaf(v, v, s); }
    g_sq[idx] = s;
}

// ---------------- fused distance GEMM + top-20 selection ------------------
// Block = 16 query rows x all 2048 columns. key[i][j] = sq_j - 2*dot(f_i,f_j)
// (same ordering as squared distance; row-constant sq_i dropped).
template<int CIN>
__global__ __launch_bounds__(256) void k_dist_topk(){
    extern __shared__ float sh[];
    float* key = sh;                 // 16*NP floats (128 KB)
    float* rf  = sh + 16*NP;         // 16*CIN floats
    const int b  = blockIdx.y;
    const int i0 = blockIdx.x * 16;
    const int tid = threadIdx.x;

    for (int idx = tid; idx < 16*CIN; idx += 256){
        int i = idx / CIN, c = idx - i*CIN;
        rf[idx] = g_feat[(b*NP + i0 + i)*CF + c];
    }
    __syncthreads();

    const float* fT = g_featT + b*CF*NP;
    #pragma unroll 1
    for (int p = 0; p < NP/256; ++p){
        int j = p*256 + tid;
        float acc[16];
        #pragma unroll
        for (int i = 0; i < 16; i++) acc[i] = 0.f;
        const float* col = fT + j;
        #pragma unroll 4
        for (int c = 0; c < CIN; c++){
            float v = __ldg(col + c*NP);
            #pragma unroll
            for (int i = 0; i < 16; i++) acc[i] = fmaf(rf[i*CIN + c], v, acc[i]);
        }
        float sqj = g_sq[b*NP + j];
        #pragma unroll
        for (int i = 0; i < 16; i++) key[i*NP + j] = fmaf(-2.f, acc[i], sqj);
    }
    __syncthreads();

    // selection: 16 groups of 16 lanes; parity stagger avoids bank conflicts
    const int r = tid >> 4, lane = tid & 15;
    const int rb = r*NP;
    const int stag = r & 1;
    for (int it = 0; it < KNN; ++it){
        float bv = 3.4e38f; int bi = NP;
        #pragma unroll 4
        for (int tt = 0; tt < NP/16; ++tt){
            int t = (tt + stag) & (NP/16 - 1);
            int j = lane + (t << 4);
            float v = key[rb + j];
            if (v < bv || (v == bv && j < bi)){ bv = v; bi = j; }
        }
        #pragma unroll
        for (int off = 8; off; off >>= 1){
            float ov = __shfl_down_sync(0xffffffffu, bv, off, 16);
            int   oi = __shfl_down_sync(0xffffffffu, bi, off, 16);
            if (ov < bv || (ov == bv && oi < bi)){ bv = ov; bi = oi; }
        }
        bi = __shfl_sync(0xffffffffu, bi, 0, 16);
        if (lane == 0){
            g_knn[(b*NP + i0 + r)*KNN + it] = bi;
            key[rb + bi] = 3.4e38f;
        }
        __syncwarp();
    }
}

// ---------------- per-point projections A = f*Wd^T, B2 = f*Wc^T -----------
template<int CIN, int COUT>
__global__ void k_proj(const float* __restrict__ W){
    __shared__ float cf[8*CIN];
    int pbase = blockIdx.x * 8;                   // 8 points per block
    int tid = threadIdx.x;
    for (int idx = tid; idx < 8*CIN; idx += COUT){
        int p = idx / CIN, c = idx - p*CIN;
        cf[idx] = g_feat[(pbase + p)*CF + c];
    }
    __syncthreads();
    const int o = tid;
    const float* Wr = W + o*2*CIN;
    #pragma unroll 1
    for (int p = 0; p < 8; p++){
        float a = 0.f, bb = 0.f;
        #pragma unroll 4
        for (int c = 0; c < CIN; c++){
            float f = cf[p*CIN + c];
            a  = fmaf(__ldg(Wr + c),        f, a);
            bb = fmaf(__ldg(Wr + CIN + c),  f, bb);
        }
        g_A [(pbase + p)*COUT + o] = a;
        g_B2[(pbase + p)*COUT + o] = bb;
    }
}

// ---------------- gather neighbors + affine + leaky + max over k ----------
template<int COUT>
__global__ void k_edge_max(const float* __restrict__ sv, const float* __restrict__ bv,
                           int offout){
    __shared__ int idxs[KNN];
    int P = blockIdx.x;                           // 0..NB*NP-1
    int o = threadIdx.x;
    if (o < KNN) idxs[o] = g_knn[P*KNN + o];
    __syncthreads();
    int b = P >> 11, n = P & (NP-1);
    float Ai = g_A[P*COUT + o];
    float Bi = g_B2[P*COUT + o];
    float base = Bi - Ai;
    float hmax = -3.4e38f, hmin = 3.4e38f;
    #pragma unroll
    for (int k = 0; k < KNN; k++){
        float v = g_A[(b*NP + idxs[k])*COUT + o] + base;
        hmax = fmaxf(hmax, v); hmin = fminf(hmin, v);
    }
    float s = sv[o], bb = bv[o];
    float y = fmaxf(lrelu(fmaf(s, hmax, bb)), lrelu(fmaf(s, hmin, bb)));
    g_feat[P*CF + offout + o] = y;
    g_featT[(b*CF + offout + o)*NP + n] = y;
}

// ---------------- W5 transpose for coalesced loads ------------------------
__global__ void k_w5t(const float* __restrict__ W5){
    int idx = blockIdx.x*256 + threadIdx.x;
    if (idx < 1024*323){
        int o = idx / 323, c = idx - o*323;
        g_W5T[c*1024 + o] = W5[idx];
    }
}

// ---------------- global 1024-ch conv + max-pool over N -------------------
__global__ __launch_bounds__(256) void k_glob(const float* __restrict__ s5,
                                              const float* __restrict__ b5){
    __shared__ float cf[16*CF];
    int b = blockIdx.z;
    int pbase = b*NP + blockIdx.x*16;
    int o = blockIdx.y*256 + threadIdx.x;
    for (int idx = threadIdx.x; idx < 16*CF; idx += 256)
        cf[idx] = g_feat[pbase*CF + idx];
    __syncthreads();
    float acc[16];
    #pragma unroll
    for (int p = 0; p < 16; p++) acc[p] = 0.f;
    const float* Wc = g_W5T + o;
    #pragma unroll 2
    for (int c = 0; c < CF; c++){
        float w = __ldg(Wc + c*1024);
        #pragma unroll
        for (int p = 0; p < 16; p++) acc[p] = fmaf(w, cf[p*CF + c], acc[p]);
    }
    float hmax = -3.4e38f, hmin = 3.4e38f;
    #pragma unroll
    for (int p = 0; p < 16; p++){ hmax = fmaxf(hmax, acc[p]); hmin = fminf(hmin, acc[p]); }
    float s = s5[o], bb = b5[o];
    float y = fmaxf(lrelu(fmaf(s, hmax, bb)), lrelu(fmaf(s, hmin, bb)));
    atomicMax(&g_gmax[b*1024 + o], enc_f(y));
}

// ---------------- decode maxpool, emit gfeat ------------------------------
__global__ void k_finalize(float* __restrict__ out){
    int i = blockIdx.x*256 + threadIdx.x;        // NB*1024 threads
    float f = dec_f(g_gmax[i]);
    g_gfeat[i] = f;
    out[NB*40 + i] = f;                           // gfeat after logits
}

// ---------------- FC head -------------------------------------------------
__global__ void k_fc(const float* __restrict__ W, const float* __restrict__ bias,
                     const float* __restrict__ sv, const float* __restrict__ Bv,
                     float* __restrict__ dout, int indim, int outdim, int layer){
    __shared__ float vin[1024];
    int b = blockIdx.x;
    const float* in = (layer == 1) ? (g_gfeat + b*1024)
                    : (layer == 2) ? (g_h1 + b*512) : (g_h2 + b*256);
    float* outp = (layer == 1) ? (g_h1 + b*512)
                : (layer == 2) ? (g_h2 + b*256) : (dout + b*40);
    for (int idx = threadIdx.x; idx < indim; idx += blockDim.x) vin[idx] = in[idx];
    __syncthreads();
    for (int o = threadIdx.x; o < outdim; o += blockDim.x){
        float a = 0.f;
        const float* Wr = W + o*indim;
        #pragma unroll 4
        for (int c = 0; c < indim; c++) a = fmaf(__ldg(Wr + c), vin[c], a);
        a += bias[o];
        if (layer != 3){
            a = fmaf(a, sv[o], Bv[o]);
            a = lrelu(a);
        }
        outp[o] = a;
    }
}

// ---------------- launch --------------------------------------------------
extern "C" void kernel_launch(void* const* d_in, const int* in_sizes, int n_in,
                              void* d_out, int out_size){
    const float* x   = (const float*)d_in[0];
    const float* W1  = (const float*)d_in[1];
    const float* s1  = (const float*)d_in[2];
    const float* b1  = (const float*)d_in[3];
    const float* W2  = (const float*)d_in[4];
    const float* s2  = (const float*)d_in[5];
    const float* b2  = (const float*)d_in[6];
    const float* W3  = (const float*)d_in[7];
    const float* s3  = (const float*)d_in[8];
    const float* b3  = (const float*)d_in[9];
    const float* W4  = (const float*)d_in[10];
    const float* s4  = (const float*)d_in[11];
    const float* b4  = (const float*)d_in[12];
    const float* W5  = (const float*)d_in[13];
    const float* s5  = (const float*)d_in[14];
    const float* b5  = (const float*)d_in[15];
    const float* fW1 = (const float*)d_in[16];
    const float* fb1 = (const float*)d_in[17];
    const float* fs1 = (const float*)d_in[18];
    const float* fB1 = (const float*)d_in[19];
    const float* fW2 = (const float*)d_in[20];
    const float* fb2 = (const float*)d_in[21];
    const float* fs2 = (const float*)d_in[22];
    const float* fB2 = (const float*)d_in[23];
    const float* fW3 = (const float*)d_in[24];
    const float* fb3 = (const float*)d_in[25];
    float* out = (float*)d_out;

    const int sm3   = (16*NP + 16*3  ) * 4;
    const int sm67  = (16*NP + 16*67 ) * 4;
    const int sm131 = (16*NP + 16*131) * 4;
    const int sm195 = (16*NP + 16*195) * 4;
    cudaFuncSetAttribute(k_dist_topk<3>,   cudaFuncAttributeMaxDynamicSharedMemorySize, sm3);
    cudaFuncSetAttribute(k_dist_topk<67>,  cudaFuncAttributeMaxDynamicSharedMemorySize, sm67);
    cudaFuncSetAttribute(k_dist_topk<131>, cudaFuncAttributeMaxDynamicSharedMemorySize, sm131);
    cudaFuncSetAttribute(k_dist_topk<195>, cudaFuncAttributeMaxDynamicSharedMemorySize, sm195);

    k_init<<<NB*NP/256, 256>>>(x);
    k_initmax<<<(NB*1024 + 255)/256, 256>>>();

    // ---- EdgeConv stage 1: Cin=3, Cout=64, out offset 3
    k_sq<<<NB*NP/256, 256>>>(3);
    k_dist_topk<3><<<dim3(NP/16, NB), 256, sm3>>>();
    k_proj<3,64><<<NB*NP/8, 64>>>(W1);
    k_edge_max<64><<<NB*NP, 64>>>(s1, b1, 3);

    // ---- EdgeConv stage 2: Cin=67, Cout=64, out offset 67
    k_sq<<<NB*NP/256, 256>>>(67);
    k_dist_topk<67><<<dim3(NP/16, NB), 256, sm67>>>();
    k_proj<67,64><<<NB*NP/8, 64>>>(W2);
    k_edge_max<64><<<NB*NP, 64>>>(s2, b2, 67);

    // ---- EdgeConv stage 3: Cin=131, Cout=64, out offset 131
    k_sq<<<NB*NP/256, 256>>>(131);
    k_dist_topk<131><<<dim3(NP/16, NB), 256, sm131>>>();
    k_proj<131,64><<<NB*NP/8, 64>>>(W3);
    k_edge_max<64><<<NB*NP, 64>>>(s3, b3, 131);

    // ---- EdgeConv stage 4: Cin=195, Cout=128, out offset 195
    k_sq<<<NB*NP/256, 256>>>(195);
    k_dist_topk<195><<<dim3(NP/16, NB), 256, sm195>>>();
    k_proj<195,128><<<NB*NP/8, 128>>>(W4);
    k_edge_max<128><<<NB*NP, 128>>>(s4, b4, 195);

    // ---- Global conv (1024) + maxpool over N
    k_w5t<<<(1024*323 + 255)/256, 256>>>(W5);
    k_glob<<<dim3(NP/16, 1024/256, NB), 256>>>(s5, b5);
    k_finalize<<<NB*1024/256, 256>>>(out);

    // ---- FC head
    k_fc<<<NB, 256>>>(fW1, fb1, fs1, fB1, out, 1024, 512, 1);
    k_fc<<<NB, 256>>>(fW2, fb2, fs2, fB2, out,  512, 256, 2);
    k_fc<<<NB, 256>>>(fW3, fb3, fs1, fB1, out,  256,  40, 3);
}

// round 2
// speedup vs baseline: 2.3631x; 2.3631x over previous
#include <cuda_runtime.h>

#define NB 8
#define NP 2048
#define KNN 20
#define CF 323
#define NEG 0.2f

typedef unsigned long long ull;

// ---------------- scratch (device globals; no allocations) ----------------
__device__ float g_feat[NB*NP*CF];      // [b][n][c] : pts|f1|f2|f3|f4
__device__ float g_featT[NB*CF*NP];     // [b][c][n]
__device__ float g_sq[NB*NP];
__device__ int   g_knn[NB*NP*KNN];
__device__ float g_A[NB*NP*128];        // feat @ Wd^T
__device__ float g_B2[NB*NP*128];       // feat @ Wc^T
__device__ float g_W5T[323*1024];
__device__ unsigned int g_gmax[NB*1024];
__device__ float g_gfeat[NB*1024];
__device__ float g_h1[NB*512];
__device__ float g_h2[NB*256];

__device__ __forceinline__ unsigned enc_f(float f){
    unsigned u = __float_as_uint(f);
    return (u & 0x80000000u) ? ~u : (u | 0x80000000u);
}
__device__ __forceinline__ float dec_f(unsigned u){
    return (u & 0x80000000u) ? __uint_as_float(u ^ 0x80000000u) : __uint_as_float(~u);
}
__device__ __forceinline__ float lrelu(float z){ return z > 0.f ? z : NEG*z; }

// packed f32x2 helpers (sm_103a FFMA2)
__device__ __forceinline__ ull pack2(float lo, float hi){
    ull r; asm("mov.b64 %0, {%1, %2};" : "=l"(r)
               : "r"(__float_as_uint(lo)), "r"(__float_as_uint(hi)));
    return r;
}
__device__ __forceinline__ void unpack2(ull v, float& lo, float& hi){
    unsigned a, b; asm("mov.b64 {%0, %1}, %2;" : "=r"(a), "=r"(b) : "l"(v));
    lo = __uint_as_float(a); hi = __uint_as_float(b);
}
__device__ __forceinline__ void fma2(ull& d, ull a, ull b){
    asm("fma.rn.f32x2 %0, %1, %2, %0;" : "+l"(d) : "l"(a), "l"(b));
}

// ---------------- init: transpose x into feat/featT, reset maxpool --------
__global__ void k_init(const float* __restrict__ x){
    int idx = blockIdx.x*256 + threadIdx.x;       // NB*NP threads
    int b = idx >> 11, n = idx & (NP-1);
    #pragma unroll
    for (int c = 0; c < 3; c++){
        float v = x[(b*3 + c)*NP + n];
        g_feat[idx*CF + c] = v;
        g_featT[(b*CF + c)*NP + n] = v;
    }
}

__global__ void k_initmax(){
    int idx = blockIdx.x*256 + threadIdx.x;
    if (idx < NB*1024) g_gmax[idx] = 0u;
}

// ---------------- squared norms over the C-prefix -------------------------
__global__ void k_sq(int cin){
    int idx = blockIdx.x*256 + threadIdx.x;       // NB*NP threads
    int b = idx >> 11, n = idx & (NP-1);
    const float* fT = g_featT + (b*CF)*NP + n;
    float s = 0.f;
    for (int c = 0; c < cin; c++){ float v = fT[c*NP]; s = fmaf(v, v, s); }
    g_sq[idx] = s;
}

// ---------------- fused distance GEMM + top-20 selection ------------------
// Block = 16 query rows x 2048 cols. key[i][j] = sq_j - 2*dot(f_i,f_j)
// GEMM: thread = 16 rows x 4 cols, rfT[c][16] smem tile, packed FFMA2.
// Selection: warp per row, 64 chunk-mins (32 elems each) as u64 (val,idx),
// warp butterfly argmin + winner-only chunk rescan per extraction.
template<int CIN>
__global__ __launch_bounds__(256) void k_dist_topk(){
    extern __shared__ float sh[];
    float* key = sh;                 // 16*NP floats (128 KB)
    float* rfT = sh + 16*NP;         // CIN*16 floats, [c][i]
    const int b  = blockIdx.y;
    const int i0 = blockIdx.x * 16;
    const int tid = threadIdx.x;

    for (int idx = tid; idx < 16*CIN; idx += 256)
        rfT[idx] = g_feat[(b*NP + i0 + (idx & 15))*CF + (idx >> 4)];
    __syncthreads();

    const float* fT = g_featT + b*CF*NP;
    #pragma unroll 1
    for (int pass = 0; pass < 2; ++pass){
        const int j0 = pass*1024 + tid*4;
        ull acc[16][2];
        #pragma unroll
        for (int i = 0; i < 16; i++){ acc[i][0] = 0ull; acc[i][1] = 0ull; }
        #pragma unroll 4
        for (int c = 0; c < CIN; ++c){
            float4 v = __ldg((const float4*)(fT + c*NP + j0));
            ull v01 = pack2(v.x, v.y), v23 = pack2(v.z, v.w);
            const float4* r4 = (const float4*)(rfT + c*16);
            #pragma unroll
            for (int q = 0; q < 4; ++q){
                float4 r = r4[q];
                ull t;
                t = pack2(r.x, r.x); fma2(acc[q*4+0][0], t, v01); fma2(acc[q*4+0][1], t, v23);
                t = pack2(r.y, r.y); fma2(acc[q*4+1][0], t, v01); fma2(acc[q*4+1][1], t, v23);
                t = pack2(r.z, r.z); fma2(acc[q*4+2][0], t, v01); fma2(acc[q*4+2][1], t, v23);
                t = pack2(r.w, r.w); fma2(acc[q*4+3][0], t, v01); fma2(acc[q*4+3][1], t, v23);
            }
        }
        float4 sq4 = __ldg((const float4*)(g_sq + b*NP + j0));
        #pragma unroll
        for (int i = 0; i < 16; i++){
            float a0,a1,a2,a3;
            unpack2(acc[i][0], a0, a1); unpack2(acc[i][1], a2, a3);
            float4 o;
            o.x = fmaf(-2.f, a0, sq4.x);
            o.y = fmaf(-2.f, a1, sq4.y);
            o.z = fmaf(-2.f, a2, sq4.z);
            o.w = fmaf(-2.f, a3, sq4.w);
            *(float4*)(key + i*NP + j0) = o;
        }
    }
    __syncthreads();

    // selection: warp w handles rows 2w, 2w+1
    const int w = tid >> 5, L = tid & 31;
    #pragma unroll 1
    for (int rr = 0; rr < 2; ++rr){
        const int r = w*2 + rr;
        float* krow = key + r*NP;
        // build 2 chunk-mins: lane L owns chunks L and L+32 (32 elems each)
        ull cm[2];
        #pragma unroll
        for (int s = 0; s < 2; ++s){
            const int base = (L + 32*s)*32;
            ull m = ~0ull;
            #pragma unroll 8
            for (int t = 0; t < 32; ++t){
                int j = base + ((t + L) & 31);           // bank-conflict-free rotation
                ull k = ((ull)enc_f(krow[j]) << 11) | (unsigned)j;
                m = (m < k) ? m : k;
            }
            cm[s] = m;
        }
        for (int it = 0; it < KNN; ++it){
            ull m = (cm[0] < cm[1]) ? cm[0] : cm[1];
            #pragma unroll
            for (int off = 16; off; off >>= 1){
                ull o = __shfl_xor_sync(0xffffffffu, m, off);
                m = (m < o) ? m : o;
            }
            int j = (int)(m & 2047u);
            if (L == 0) g_knn[(b*NP + i0 + r)*KNN + it] = j;
            int ch = j >> 5;
            if ((ch & 31) == L){
                krow[j] = __int_as_float(0x7f800000);    // +inf -> excluded
                int base = ch*32;
                ull mm = ~0ull;
                #pragma unroll 8
                for (int t = 0; t < 32; ++t){
                    int jj = base + t;
                    ull k = ((ull)enc_f(krow[jj]) << 11) | (unsigned)jj;
                    mm = (mm < k) ? mm : k;
                }
                cm[ch >> 5] = mm;
            }
            __syncwarp();
        }
    }
}

// ---------------- per-point projections A = f*Wd^T, B2 = f*Wc^T -----------
// 16 points per block, COUT threads, c-outer loop, packed FFMA2.
template<int CIN, int COUT>
__global__ void k_proj(const float* __restrict__ W){
    __shared__ float cfT[CIN*16];                 // [c][p]
    int pbase = blockIdx.x * 16;
    int tid = threadIdx.x;                        // = out channel
    for (int idx = tid; idx < 16*CIN; idx += COUT)
        cfT[idx] = g_feat[(pbase + (idx & 15))*CF + (idx >> 4)];
    __syncthreads();
    const float* Wd = W + tid*2*CIN;
    const float* Wc = Wd + CIN;
    ull acca[8], accb[8];
    #pragma unroll
    for (int q = 0; q < 8; q++){ acca[q] = 0ull; accb[q] = 0ull; }
    #pragma unroll 4
    for (int c = 0; c < CIN; ++c){
        float wd = __ldg(Wd + c), wc = __ldg(Wc + c);
        ull wdp = pack2(wd, wd), wcp = pack2(wc, wc);
        const float4* p4 = (const float4*)(cfT + c*16);
        #pragma unroll
        for (int q = 0; q < 4; ++q){
            float4 pv = p4[q];
            ull p01 = pack2(pv.x, pv.y), p23 = pack2(pv.z, pv.w);
            fma2(acca[q*2  ], wdp, p01); fma2(acca[q*2+1], wdp, p23);
            fma2(accb[q*2  ], wcp, p01); fma2(accb[q*2+1], wcp, p23);
        }
    }
    #pragma unroll
    for (int q = 0; q < 8; ++q){
        float a0, a1, b0, b1;
        unpack2(acca[q], a0, a1); unpack2(accb[q], b0, b1);
        int p = q*2;
        g_A [(pbase + p    )*COUT + tid] = a0;
        g_A [(pbase + p + 1)*COUT + tid] = a1;
        g_B2[(pbase + p    )*COUT + tid] = b0;
        g_B2[(pbase + p + 1)*COUT + tid] = b1;
    }
}

// ---------------- gather neighbors + affine + leaky + max over k ----------
template<int COUT>
__global__ void k_edge_max(const float* __restrict__ sv, const float* __restrict__ bv,
                           int offout){
    __shared__ int idxs[KNN];
    int P = blockIdx.x;                           // 0..NB*NP-1
    int o = threadIdx.x;
    if (o < KNN) idxs[o] = g_knn[P*KNN + o];
    __syncthreads();
    int b = P >> 11, n = P & (NP-1);
    float Ai = g_A[P*COUT + o];
    float Bi = g_B2[P*COUT + o];
    float base = Bi - Ai;
    float hmax = -3.4e38f, hmin = 3.4e38f;
    #pragma unroll
    for (int k = 0; k < KNN; k++){
        float v = g_A[(b*NP + idxs[k])*COUT + o] + base;
        hmax = fmaxf(hmax, v); hmin = fminf(hmin, v);
    }
    float s = sv[o], bb = bv[o];
    float y = fmaxf(lrelu(fmaf(s, hmax, bb)), lrelu(fmaf(s, hmin, bb)));
    g_feat[P*CF + offout + o] = y;
    g_featT[(b*CF + offout + o)*NP + n] = y;
}

// ---------------- W5 transpose for coalesced loads ------------------------
__global__ void k_w5t(const float* __restrict__ W5){
    int idx = blockIdx.x*256 + threadIdx.x;
    if (idx < 1024*323){
        int o = idx / 323, c = idx - o*323;
        g_W5T[c*1024 + o] = W5[idx];
    }
}

// ---------------- global 1024-ch conv + max-pool over N -------------------
// 32 points x 512 outs per block; thread = 32 points x 2 outs, packed FFMA2.
__global__ __launch_bounds__(256) void k_glob(const float* __restrict__ s5,
                                              const float* __restrict__ b5){
    __shared__ float cfT[CF*32];                  // [c][p], 41.3 KB
    int b = blockIdx.z;
    int p0 = blockIdx.x*32;
    for (int idx = threadIdx.x; idx < 32*CF; idx += 256){
        int p = idx / CF, c = idx - p*CF;
        cfT[c*32 + p] = g_feat[(b*NP + p0 + p)*CF + c];
    }
    __syncthreads();
    int o = blockIdx.y*512 + threadIdx.x*2;
    ull acc0[16], acc1[16];
    #pragma unroll
    for (int q = 0; q < 16; q++){ acc0[q] = 0ull; acc1[q] = 0ull; }
    const float* Wc = g_W5T + o;
    #pragma unroll 2
    for (int c = 0; c < CF; ++c){
        float2 wv = __ldg((const float2*)(Wc + c*1024));
        ull w0 = pack2(wv.x, wv.x), w1 = pack2(wv.y, wv.y);
        const float4* p4 = (const float4*)(cfT + c*32);
        #pragma unroll
        for (int q = 0; q < 8; ++q){
            float4 pv = p4[q];
            ull p01 = pack2(pv.x, pv.y), p23 = pack2(pv.z, pv.w);
            fma2(acc0[q*2  ], w0, p01); fma2(acc0[q*2+1], w0, p23);
            fma2(acc1[q*2  ], w1, p01); fma2(acc1[q*2+1], w1, p23);
        }
    }
    #pragma unroll
    for (int k = 0; k < 2; ++k){
        ull* a = k ? acc1 : acc0;
        float hmax = -3.4e38f, hmin = 3.4e38f;
        #pragma unroll
        for (int q = 0; q < 16; ++q){
            float x0, x1; unpack2(a[q], x0, x1);
            hmax = fmaxf(hmax, fmaxf(x0, x1));
            hmin = fminf(hmin, fminf(x0, x1));
        }
        float s = s5[o + k], bb = b5[o + k];
        float y = fmaxf(lrelu(fmaf(s, hmax, bb)), lrelu(fmaf(s, hmin, bb)));
        atomicMax(&g_gmax[b*1024 + o + k], enc_f(y));
    }
}

// ---------------- decode maxpool, emit gfeat ------------------------------
__global__ void k_finalize(float* __restrict__ out){
    int i = blockIdx.x*256 + threadIdx.x;        // NB*1024 threads
    float f = dec_f(g_gmax[i]);
    g_gfeat[i] = f;
    out[NB*40 + i] = f;                           // gfeat after logits
}

// ---------------- FC head -------------------------------------------------
__global__ void k_fc(const float* __restrict__ W, const float* __restrict__ bias,
                     const float* __restrict__ sv, const float* __restrict__ Bv,
                     float* __restrict__ dout, int indim, int outdim, int layer){
    __shared__ float vin[1024];
    int b = blockIdx.x;
    const float* in = (layer == 1) ? (g_gfeat + b*1024)
                    : (layer == 2) ? (g_h1 + b*512) : (g_h2 + b*256);
    float* outp = (layer == 1) ? (g_h1 + b*512)
                : (layer == 2) ? (g_h2 + b*256) : (dout + b*40);
    for (int idx = threadIdx.x; idx < indim; idx += blockDim.x) vin[idx] = in[idx];
    __syncthreads();
    for (int o = threadIdx.x; o < outdim; o += blockDim.x){
        float a = 0.f;
        const float* Wr = W + o*indim;
        #pragma unroll 4
        for (int c = 0; c < indim; c++) a = fmaf(__ldg(Wr + c), vin[c], a);
        a += bias[o];
        if (layer != 3){
            a = fmaf(a, sv[o], Bv[o]);
            a = lrelu(a);
        }
        outp[o] = a;
    }
}

// ---------------- launch --------------------------------------------------
extern "C" void kernel_launch(void* const* d_in, const int* in_sizes, int n_in,
                              void* d_out, int out_size){
    const float* x   = (const float*)d_in[0];
    const float* W1  = (const float*)d_in[1];
    const float* s1  = (const float*)d_in[2];
    const float* b1  = (const float*)d_in[3];
    const float* W2  = (const float*)d_in[4];
    const float* s2  = (const float*)d_in[5];
    const float* b2  = (const float*)d_in[6];
    const float* W3  = (const float*)d_in[7];
    const float* s3  = (const float*)d_in[8];
    const float* b3  = (const float*)d_in[9];
    const float* W4  = (const float*)d_in[10];
    const float* s4  = (const float*)d_in[11];
    const float* b4  = (const float*)d_in[12];
    const float* W5  = (const float*)d_in[13];
    const float* s5  = (const float*)d_in[14];
    const float* b5  = (const float*)d_in[15];
    const float* fW1 = (const float*)d_in[16];
    const float* fb1 = (const float*)d_in[17];
    const float* fs1 = (const float*)d_in[18];
    const float* fB1 = (const float*)d_in[19];
    const float* fW2 = (const float*)d_in[20];
    const float* fb2 = (const float*)d_in[21];
    const float* fs2 = (const float*)d_in[22];
    const float* fB2 = (const float*)d_in[23];
    const float* fW3 = (const float*)d_in[24];
    const float* fb3 = (const float*)d_in[25];
    float* out = (float*)d_out;

    const int sm3   = (16*NP + 16*3  ) * 4;
    const int sm67  = (16*NP + 16*67 ) * 4;
    const int sm131 = (16*NP + 16*131) * 4;
    const int sm195 = (16*NP + 16*195) * 4;
    cudaFuncSetAttribute(k_dist_topk<3>,   cudaFuncAttributeMaxDynamicSharedMemorySize, sm3);
    cudaFuncSetAttribute(k_dist_topk<67>,  cudaFuncAttributeMaxDynamicSharedMemorySize, sm67);
    cudaFuncSetAttribute(k_dist_topk<131>, cudaFuncAttributeMaxDynamicSharedMemorySize, sm131);
    cudaFuncSetAttribute(k_dist_topk<195>, cudaFuncAttributeMaxDynamicSharedMemorySize, sm195);

    k_init<<<NB*NP/256, 256>>>(x);
    k_initmax<<<(NB*1024 + 255)/256, 256>>>();

    // ---- EdgeConv stage 1: Cin=3, Cout=64, out offset 3
    k_sq<<<NB*NP/256, 256>>>(3);
    k_dist_topk<3><<<dim3(NP/16, NB), 256, sm3>>>();
    k_proj<3,64><<<NB*NP/16, 64>>>(W1);
    k_edge_max<64><<<NB*NP, 64>>>(s1, b1, 3);

    // ---- EdgeConv stage 2: Cin=67, Cout=64, out offset 67
    k_sq<<<NB*NP/256, 256>>>(67);
    k_dist_topk<67><<<dim3(NP/16, NB), 256, sm67>>>();
    k_proj<67,64><<<NB*NP/16, 64>>>(W2);
    k_edge_max<64><<<NB*NP, 64>>>(s2, b2, 67);

    // ---- EdgeConv stage 3: Cin=131, Cout=64, out offset 131
    k_sq<<<NB*NP/256, 256>>>(131);
    k_dist_topk<131><<<dim3(NP/16, NB), 256, sm131>>>();
    k_proj<131,64><<<NB*NP/16, 64>>>(W3);
    k_edge_max<64><<<NB*NP, 64>>>(s3, b3, 131);

    // ---- EdgeConv stage 4: Cin=195, Cout=128, out offset 195
    k_sq<<<NB*NP/256, 256>>>(195);
    k_dist_topk<195><<<dim3(NP/16, NB), 256, sm195>>>();
    k_proj<195,128><<<NB*NP/16, 128>>>(W4);
    k_edge_max<128><<<NB*NP, 128>>>(s4, b4, 195);

    // ---- Global conv (1024) + maxpool over N
    k_w5t<<<(1024*323 + 255)/256, 256>>>(W5);
    k_glob<<<dim3(NP/32, 2, NB), 256>>>(s5, b5);
    k_finalize<<<NB*1024/256, 256>>>(out);

    // ---- FC head
    k_fc<<<NB, 256>>>(fW1, fb1, fs1, fB1, out, 1024, 512, 1);
    k_fc<<<NB, 256>>>(fW2, fb2, fs2, fB2, out,  512, 256, 2);
    k_fc<<<NB, 256>>>(fW3, fb3, fs1, fB1, out,  256,  40, 3);
}

// round 3
// speedup vs baseline: 3.2945x; 1.3941x over previous
#include <cuda_runtime.h>

#define NB 8
#define NP 2048
#define KNN 20
#define CF 323
#define NEG 0.2f
#define FINF __int_as_float(0x7f800000)

typedef unsigned long long ull;

// ---------------- scratch (device globals; no allocations) ----------------
__device__ float g_feat[NB*NP*CF];      // [b][n][c] : pts|f1|f2|f3|f4
__device__ float g_featT[NB*CF*NP];     // [b][c][n]
__device__ float g_sq[NB*NP];
__device__ int   g_knn[NB*NP*KNN];
__device__ float g_A[NB*NP*128];        // feat @ Wd^T
__device__ float g_B2[NB*NP*128];       // feat @ Wc^T
__device__ float g_W5T[323*1024];
__device__ unsigned int g_gmax[NB*1024];
__device__ float g_gfeat[NB*1024];
__device__ float g_h1[NB*512];
__device__ float g_h2[NB*256];

__device__ __forceinline__ unsigned enc_f(float f){
    unsigned u = __float_as_uint(f);
    return (u & 0x80000000u) ? ~u : (u | 0x80000000u);
}
__device__ __forceinline__ float dec_f(unsigned u){
    return (u & 0x80000000u) ? __uint_as_float(u ^ 0x80000000u) : __uint_as_float(~u);
}
__device__ __forceinline__ float lrelu(float z){ return z > 0.f ? z : NEG*z; }

// packed f32x2 helpers (sm_103a FFMA2)
__device__ __forceinline__ ull pack2(float lo, float hi){
    ull r; asm("mov.b64 %0, {%1, %2};" : "=l"(r)
               : "r"(__float_as_uint(lo)), "r"(__float_as_uint(hi)));
    return r;
}
__device__ __forceinline__ void unpack2(ull v, float& lo, float& hi){
    unsigned a, b; asm("mov.b64 {%0, %1}, %2;" : "=r"(a), "=r"(b) : "l"(v));
    lo = __uint_as_float(a); hi = __uint_as_float(b);
}
__device__ __forceinline__ void fma2(ull& d, ull a, ull b){
    asm("fma.rn.f32x2 %0, %1, %2, %0;" : "+l"(d) : "l"(a), "l"(b));
}

// ---------------- init: transpose x into feat/featT, reset maxpool --------
__global__ void k_init(const float* __restrict__ x){
    int idx = blockIdx.x*256 + threadIdx.x;       // NB*NP threads
    int b = idx >> 11, n = idx & (NP-1);
    #pragma unroll
    for (int c = 0; c < 3; c++){
        float v = x[(b*3 + c)*NP + n];
        g_feat[idx*CF + c] = v;
        g_featT[(b*CF + c)*NP + n] = v;
    }
}

__global__ void k_initmax(){
    int idx = blockIdx.x*256 + threadIdx.x;
    if (idx < NB*1024) g_gmax[idx] = 0u;
}

// ---------------- squared norms: incremental over new channel block -------
__global__ void k_sq_add(int c0, int c1, int init){
    int idx = blockIdx.x*256 + threadIdx.x;       // NB*NP threads
    int b = idx >> 11, n = idx & (NP-1);
    const float* fT = g_featT + (b*CF)*NP + n;
    float s = init ? 0.f : g_sq[idx];
    for (int c = c0; c < c1; c++){ float v = fT[c*NP]; s = fmaf(v, v, s); }
    g_sq[idx] = s;
}

// ---------------- fused distance GEMM + top-20 selection ------------------
// Block = 16 query rows x 2048 cols. key[i][j] = sq_j - 2*dot(f_i,f_j)
// GEMM: thread = 16 rows x 4 cols, rfT[c][16] smem tile, packed FFMA2.
// Selection: warp per row; 64 float chunk-mins (32 elems) held 2/lane;
// extraction = value butterfly min + equality-ballot localization +
// full-warp chunk-min rebuild. Lowest-index tie-break preserved.
template<int CIN>
__global__ __launch_bounds__(256) void k_dist_topk(){
    extern __shared__ float sh[];
    float* key = sh;                 // 16*NP floats (128 KB)
    float* rfT = sh + 16*NP;         // CIN*16 floats, [c][i]
    const int b  = blockIdx.y;
    const int i0 = blockIdx.x * 16;
    const int tid = threadIdx.x;

    for (int idx = tid; idx < 16*CIN; idx += 256)
        rfT[idx] = g_feat[(b*NP + i0 + (idx & 15))*CF + (idx >> 4)];
    __syncthreads();

    const float* fT = g_featT + b*CF*NP;
    #pragma unroll 1
    for (int pass = 0; pass < 2; ++pass){
        const int j0 = pass*1024 + tid*4;
        ull acc[16][2];
        #pragma unroll
        for (int i = 0; i < 16; i++){ acc[i][0] = 0ull; acc[i][1] = 0ull; }
        #pragma unroll 4
        for (int c = 0; c < CIN; ++c){
            float4 v = __ldg((const float4*)(fT + c*NP + j0));
            ull v01 = pack2(v.x, v.y), v23 = pack2(v.z, v.w);
            const float4* r4 = (const float4*)(rfT + c*16);
            #pragma unroll
            for (int q = 0; q < 4; ++q){
                float4 r = r4[q];
                ull t;
                t = pack2(r.x, r.x); fma2(acc[q*4+0][0], t, v01); fma2(acc[q*4+0][1], t, v23);
                t = pack2(r.y, r.y); fma2(acc[q*4+1][0], t, v01); fma2(acc[q*4+1][1], t, v23);
                t = pack2(r.z, r.z); fma2(acc[q*4+2][0], t, v01); fma2(acc[q*4+2][1], t, v23);
                t = pack2(r.w, r.w); fma2(acc[q*4+3][0], t, v01); fma2(acc[q*4+3][1], t, v23);
            }
        }
        float4 sq4 = __ldg((const float4*)(g_sq + b*NP + j0));
        #pragma unroll
        for (int i = 0; i < 16; i++){
            float a0,a1,a2,a3;
            unpack2(acc[i][0], a0, a1); unpack2(acc[i][1], a2, a3);
            float4 o;
            o.x = fmaf(-2.f, a0, sq4.x);
            o.y = fmaf(-2.f, a1, sq4.y);
            o.z = fmaf(-2.f, a2, sq4.z);
            o.w = fmaf(-2.f, a3, sq4.w);
            *(float4*)(key + i*NP + j0) = o;
        }
    }
    __syncthreads();

    // ---- selection: warp w handles rows 2w, 2w+1
    const int w = tid >> 5, L = tid & 31;
    #pragma unroll 1
    for (int rr = 0; rr < 2; ++rr){
        const int r = w*2 + rr;
        float* krow = key + r*NP;
        // build 2 chunk-mins per lane (chunks L and L+32), rotated float4 loads
        float cm0 = FINF, cm1 = FINF;
        {
            const float4* c4 = (const float4*)(krow + L*32);
            const float4* d4 = (const float4*)(krow + (L + 32)*32);
            #pragma unroll
            for (int t = 0; t < 8; ++t){
                int tt = (t + L) & 7;
                float4 u = c4[tt];
                cm0 = fminf(cm0, fminf(fminf(u.x, u.y), fminf(u.z, u.w)));
                float4 v = d4[tt];
                cm1 = fminf(cm1, fminf(fminf(v.x, v.y), fminf(v.z, v.w)));
            }
        }
        int* knnp = g_knn + (b*NP + i0 + r)*KNN;
        for (int it = 0; it < KNN; ++it){
            // global min value
            float m = fminf(cm0, cm1);
            #pragma unroll
            for (int off = 16; off; off >>= 1)
                m = fminf(m, __shfl_xor_sync(0xffffffffu, m, off));
            // lowest chunk containing m
            unsigned e0 = __ballot_sync(0xffffffffu, cm0 == m);
            unsigned e1 = __ballot_sync(0xffffffffu, cm1 == m);
            int ch = e0 ? (__ffs(e0) - 1) : (32 + __ffs(e1) - 1);
            // lowest index within chunk (one element per lane)
            float v = krow[ch*32 + L];
            unsigned eq = __ballot_sync(0xffffffffu, v == m);
            int jl = __ffs(eq) - 1;
            int j = ch*32 + jl;
            if (L == jl){ krow[j] = FINF; v = FINF; }
            if (L == 0) knnp[it] = j;
            // rebuild chunk min (full-warp butterfly over v)
            float nm = v;
            #pragma unroll
            for (int off = 16; off; off >>= 1)
                nm = fminf(nm, __shfl_xor_sync(0xffffffffu, nm, off));
            if (L == (ch & 31)){
                if (ch < 32) cm0 = nm; else cm1 = nm;
            }
        }
    }
}

// ---------------- per-point projections A = f*Wd^T, B2 = f*Wc^T -----------
// 16 points per block, COUT threads, c-outer loop, packed FFMA2.
template<int CIN, int COUT>
__global__ void k_proj(const float* __restrict__ W){
    __shared__ float cfT[CIN*16];                 // [c][p]
    int pbase = blockIdx.x * 16;
    int tid = threadIdx.x;                        // = out channel
    for (int idx = tid; idx < 16*CIN; idx += COUT)
        cfT[idx] = g_feat[(pbase + (idx & 15))*CF + (idx >> 4)];
    __syncthreads();
    const float* Wd = W + tid*2*CIN;
    const float* Wc = Wd + CIN;
    ull acca[8], accb[8];
    #pragma unroll
    for (int q = 0; q < 8; q++){ acca[q] = 0ull; accb[q] = 0ull; }
    #pragma unroll 4
    for (int c = 0; c < CIN; ++c){
        float wd = __ldg(Wd + c), wc = __ldg(Wc + c);
        ull wdp = pack2(wd, wd), wcp = pack2(wc, wc);
        const float4* p4 = (const float4*)(cfT + c*16);
        #pragma unroll
        for (int q = 0; q < 4; ++q){
            float4 pv = p4[q];
            ull p01 = pack2(pv.x, pv.y), p23 = pack2(pv.z, pv.w);
            fma2(acca[q*2  ], wdp, p01); fma2(acca[q*2+1], wdp, p23);
            fma2(accb[q*2  ], wcp, p01); fma2(accb[q*2+1], wcp, p23);
        }
    }
    #pragma unroll
    for (int q = 0; q < 8; ++q){
        float a0, a1, b0, b1;
        unpack2(acca[q], a0, a1); unpack2(accb[q], b0, b1);
        int p = q*2;
        g_A [(pbase + p    )*COUT + tid] = a0;
        g_A [(pbase + p + 1)*COUT + tid] = a1;
        g_B2[(pbase + p    )*COUT + tid] = b0;
        g_B2[(pbase + p + 1)*COUT + tid] = b1;
    }
}

// ---------------- gather neighbors + affine + leaky + max over k ----------
// 4 points per block.
template<int COUT>
__global__ void k_edge_max(const float* __restrict__ sv, const float* __restrict__ bv,
                           int offout){
    __shared__ int idxs[4*KNN];
    int P0 = blockIdx.x*4;
    int t = threadIdx.x;
    if (t < 4*KNN) idxs[t] = g_knn[P0*KNN + t];
    __syncthreads();
    int p = t / COUT, o = t - p*COUT;
    int P = P0 + p;
    int b = P >> 11, n = P & (NP-1);
    float Ai = g_A[P*COUT + o];
    float Bi = g_B2[P*COUT + o];
    float base = Bi - Ai;
    float hmax = -3.4e38f, hmin = 3.4e38f;
    const int* ip = idxs + p*KNN;
    #pragma unroll
    for (int k = 0; k < KNN; k++){
        float v = g_A[(b*NP + ip[k])*COUT + o] + base;
        hmax = fmaxf(hmax, v); hmin = fminf(hmin, v);
    }
    float s = sv[o], bb = bv[o];
    float y = fmaxf(lrelu(fmaf(s, hmax, bb)), lrelu(fmaf(s, hmin, bb)));
    g_feat[P*CF + offout + o] = y;
    g_featT[(b*CF + offout + o)*NP + n] = y;
}

// ---------------- W5 transpose for coalesced loads ------------------------
__global__ void k_w5t(const float* __restrict__ W5){
    int idx = blockIdx.x*256 + threadIdx.x;
    if (idx < 1024*323){
        int o = idx / 323, c = idx - o*323;
        g_W5T[c*1024 + o] = W5[idx];
    }
}

// ---------------- global 1024-ch conv + max-pool over N -------------------
// 32 points x 512 outs per block; thread = 32 points x 2 outs, packed FFMA2.
__global__ __launch_bounds__(256) void k_glob(const float* __restrict__ s5,
                                              const float* __restrict__ b5){
    __shared__ float cfT[CF*32];                  // [c][p], 41.3 KB
    int b = blockIdx.z;
    int p0 = blockIdx.x*32;
    for (int idx = threadIdx.x; idx < 32*CF; idx += 256){
        int p = idx / CF, c = idx - p*CF;
        cfT[c*32 + p] = g_feat[(b*NP + p0 + p)*CF + c];
    }
    __syncthreads();
    int o = blockIdx.y*512 + threadIdx.x*2;
    ull acc0[16], acc1[16];
    #pragma unroll
    for (int q = 0; q < 16; q++){ acc0[q] = 0ull; acc1[q] = 0ull; }
    const float* Wc = g_W5T + o;
    #pragma unroll 2
    for (int c = 0; c < CF; ++c){
        float2 wv = __ldg((const float2*)(Wc + c*1024));
        ull w0 = pack2(wv.x, wv.x), w1 = pack2(wv.y, wv.y);
        const float4* p4 = (const float4*)(cfT + c*32);
        #pragma unroll
        for (int q = 0; q < 8; ++q){
            float4 pv = p4[q];
            ull p01 = pack2(pv.x, pv.y), p23 = pack2(pv.z, pv.w);
            fma2(acc0[q*2  ], w0, p01); fma2(acc0[q*2+1], w0, p23);
            fma2(acc1[q*2  ], w1, p01); fma2(acc1[q*2+1], w1, p23);
        }
    }
    #pragma unroll
    for (int k = 0; k < 2; ++k){
        ull* a = k ? acc1 : acc0;
        float hmax = -3.4e38f, hmin = 3.4e38f;
        #pragma unroll
        for (int q = 0; q < 16; ++q){
            float x0, x1; unpack2(a[q], x0, x1);
            hmax = fmaxf(hmax, fmaxf(x0, x1));
            hmin = fminf(hmin, fminf(x0, x1));
        }
        float s = s5[o + k], bb = b5[o + k];
        float y = fmaxf(lrelu(fmaf(s, hmax, bb)), lrelu(fmaf(s, hmin, bb)));
        atomicMax(&g_gmax[b*1024 + o + k], enc_f(y));
    }
}

// ---------------- decode maxpool, emit gfeat ------------------------------
__global__ void k_finalize(float* __restrict__ out){
    int i = blockIdx.x*256 + threadIdx.x;        // NB*1024 threads
    float f = dec_f(g_gmax[i]);
    g_gfeat[i] = f;
    out[NB*40 + i] = f;                           // gfeat after logits
}

// ---------------- FC head -------------------------------------------------
__global__ void k_fc(const float* __restrict__ W, const float* __restrict__ bias,
                     const float* __restrict__ sv, const float* __restrict__ Bv,
                     float* __restrict__ dout, int indim, int outdim, int layer){
    __shared__ float vin[1024];
    int b = blockIdx.x;
    const float* in = (layer == 1) ? (g_gfeat + b*1024)
                    : (layer == 2) ? (g_h1 + b*512) : (g_h2 + b*256);
    float* outp = (layer == 1) ? (g_h1 + b*512)
                : (layer == 2) ? (g_h2 + b*256) : (dout + b*40);
    for (int idx = threadIdx.x; idx < indim; idx += blockDim.x) vin[idx] = in[idx];
    __syncthreads();
    for (int o = threadIdx.x; o < outdim; o += blockDim.x){
        float a = 0.f;
        const float* Wr = W + o*indim;
        #pragma unroll 4
        for (int c = 0; c < indim; c++) a = fmaf(__ldg(Wr + c), vin[c], a);
        a += bias[o];
        if (layer != 3){
            a = fmaf(a, sv[o], Bv[o]);
            a = lrelu(a);
        }
        outp[o] = a;
    }
}

// ---------------- launch --------------------------------------------------
extern "C" void kernel_launch(void* const* d_in, const int* in_sizes, int n_in,
                              void* d_out, int out_size){
    const float* x   = (const float*)d_in[0];
    const float* W1  = (const float*)d_in[1];
    const float* s1  = (const float*)d_in[2];
    const float* b1  = (const float*)d_in[3];
    const float* W2  = (const float*)d_in[4];
    const float* s2  = (const float*)d_in[5];
    const float* b2  = (const float*)d_in[6];
    const float* W3  = (const float*)d_in[7];
    const float* s3  = (const float*)d_in[8];
    const float* b3  = (const float*)d_in[9];
    const float* W4  = (const float*)d_in[10];
    const float* s4  = (const float*)d_in[11];
    const float* b4  = (const float*)d_in[12];
    const float* W5  = (const float*)d_in[13];
    const float* s5  = (const float*)d_in[14];
    const float* b5  = (const float*)d_in[15];
    const float* fW1 = (const float*)d_in[16];
    const float* fb1 = (const float*)d_in[17];
    const float* fs1 = (const float*)d_in[18];
    const float* fB1 = (const float*)d_in[19];
    const float* fW2 = (const float*)d_in[20];
    const float* fb2 = (const float*)d_in[21];
    const float* fs2 = (const float*)d_in[22];
    const float* fB2 = (const float*)d_in[23];
    const float* fW3 = (const float*)d_in[24];
    const float* fb3 = (const float*)d_in[25];
    float* out = (float*)d_out;

    const int sm3   = (16*NP + 16*3  ) * 4;
    const int sm67  = (16*NP + 16*67 ) * 4;
    const int sm131 = (16*NP + 16*131) * 4;
    const int sm195 = (16*NP + 16*195) * 4;
    cudaFuncSetAttribute(k_dist_topk<3>,   cudaFuncAttributeMaxDynamicSharedMemorySize, sm3);
    cudaFuncSetAttribute(k_dist_topk<67>,  cudaFuncAttributeMaxDynamicSharedMemorySize, sm67);
    cudaFuncSetAttribute(k_dist_topk<131>, cudaFuncAttributeMaxDynamicSharedMemorySize, sm131);
    cudaFuncSetAttribute(k_dist_topk<195>, cudaFuncAttributeMaxDynamicSharedMemorySize, sm195);

    k_init<<<NB*NP/256, 256>>>(x);
    k_initmax<<<(NB*1024 + 255)/256, 256>>>();

    // ---- EdgeConv stage 1: Cin=3, Cout=64, out offset 3
    k_sq_add<<<NB*NP/256, 256>>>(0, 3, 1);
    k_dist_topk<3><<<dim3(NP/16, NB), 256, sm3>>>();
    k_proj<3,64><<<NB*NP/16, 64>>>(W1);
    k_edge_max<64><<<NB*NP/4, 256>>>(s1, b1, 3);

    // ---- EdgeConv stage 2: Cin=67, Cout=64, out offset 67
    k_sq_add<<<NB*NP/256, 256>>>(3, 67, 0);
    k_dist_topk<67><<<dim3(NP/16, NB), 256, sm67>>>();
    k_proj<67,64><<<NB*NP/16, 64>>>(W2);
    k_edge_max<64><<<NB*NP/4, 256>>>(s2, b2, 67);

    // ---- EdgeConv stage 3: Cin=131, Cout=64, out offset 131
    k_sq_add<<<NB*NP/256, 256>>>(67, 131, 0);
    k_dist_topk<131><<<dim3(NP/16, NB), 256, sm131>>>();
    k_proj<131,64><<<NB*NP/16, 64>>>(W3);
    k_edge_max<64><<<NB*NP/4, 256>>>(s3, b3, 131);

    // ---- EdgeConv stage 4: Cin=195, Cout=128, out offset 195
    k_sq_add<<<NB*NP/256, 256>>>(131, 195, 0);
    k_dist_topk<195><<<dim3(NP/16, NB), 256, sm195>>>();
    k_proj<195,128><<<NB*NP/16, 128>>>(W4);
    k_edge_max<128><<<NB*NP/4, 512>>>(s4, b4, 195);

    // ---- Global conv (1024) + maxpool over N
    k_w5t<<<(1024*323 + 255)/256, 256>>>(W5);
    k_glob<<<dim3(NP/32, 2, NB), 256>>>(s5, b5);
    k_finalize<<<NB*1024/256, 256>>>(out);

    // ---- FC head
    k_fc<<<NB, 256>>>(fW1, fb1, fs1, fB1, out, 1024, 512, 1);
    k_fc<<<NB, 256>>>(fW2, fb2, fs2, fB2, out,  512, 256, 2);
    k_fc<<<NB, 256>>>(fW3, fb3, fs1, fB1, out,  256,  40, 3);
}

// round 4
// speedup vs baseline: 4.6464x; 1.4104x over previous
#include <cuda_runtime.h>

#define NB 8
#define NP 2048
#define KNN 20
#define CF 323
#define NEG 0.2f
#define FINF __int_as_float(0x7f800000)

typedef unsigned long long ull;

// ---------------- scratch (device globals; no allocations) ----------------
__device__ float g_feat[NB*NP*CF];      // [b][n][c] : pts|f1|f2|f3|f4
__device__ float g_featT[NB*CF*NP];     // [b][c][n]
__device__ float g_sq[NB*NP];
__device__ int   g_knn[NB*NP*KNN];
__device__ float g_A[NB*NP*128];        // feat @ Wd^T
__device__ float g_B2[NB*NP*128];       // feat @ Wc^T
__device__ float g_dot[NB*NP*NP];       // running pairwise dot products (134 MB)
__device__ float g_W5T[323*1024];
__device__ unsigned int g_gmax[NB*1024];
__device__ float g_gfeat[NB*1024];
__device__ float g_h1[NB*512];
__device__ float g_h2[NB*256];

__device__ __forceinline__ unsigned enc_f(float f){
    unsigned u = __float_as_uint(f);
    return (u & 0x80000000u) ? ~u : (u | 0x80000000u);
}
__device__ __forceinline__ float dec_f(unsigned u){
    return (u & 0x80000000u) ? __uint_as_float(u ^ 0x80000000u) : __uint_as_float(~u);
}
__device__ __forceinline__ float lrelu(float z){ return z > 0.f ? z : NEG*z; }

// packed f32x2 helpers (sm_103a FFMA2)
__device__ __forceinline__ ull pack2(float lo, float hi){
    ull r; asm("mov.b64 %0, {%1, %2};" : "=l"(r)
               : "r"(__float_as_uint(lo)), "r"(__float_as_uint(hi)));
    return r;
}
__device__ __forceinline__ void unpack2(ull v, float& lo, float& hi){
    unsigned a, b; asm("mov.b64 {%0, %1}, %2;" : "=r"(a), "=r"(b) : "l"(v));
    lo = __uint_as_float(a); hi = __uint_as_float(b);
}
__device__ __forceinline__ void fma2(ull& d, ull a, ull b){
    asm("fma.rn.f32x2 %0, %1, %2, %0;" : "+l"(d) : "l"(a), "l"(b));
}

// ---------------- init: transpose x into feat/featT, reset maxpool --------
__global__ void k_init(const float* __restrict__ x){
    int idx = blockIdx.x*256 + threadIdx.x;       // NB*NP threads
    int b = idx >> 11, n = idx & (NP-1);
    #pragma unroll
    for (int c = 0; c < 3; c++){
        float v = x[(b*3 + c)*NP + n];
        g_feat[idx*CF + c] = v;
        g_featT[(b*CF + c)*NP + n] = v;
    }
}

__global__ void k_initmax(){
    int idx = blockIdx.x*256 + threadIdx.x;
    if (idx < NB*1024) g_gmax[idx] = 0u;
}

// ---------------- squared norms: incremental over new channel block -------
__global__ void k_sq_add(int c0, int c1, int init){
    int idx = blockIdx.x*256 + threadIdx.x;       // NB*NP threads
    int b = idx >> 11, n = idx & (NP-1);
    const float* fT = g_featT + (b*CF)*NP + n;
    float s = init ? 0.f : g_sq[idx];
    for (int c = c0; c < c1; c++){ float v = fT[c*NP]; s = fmaf(v, v, s); }
    g_sq[idx] = s;
}

// ---------------- fused incremental-dot GEMM + top-20 selection -----------
// Block = 8 query rows x 2048 cols (64KB key -> 3 CTAs/SM).
// dot accumulates across stages in g_dot; this stage adds channels [C0,C1).
// key[i][j] = sq_j - 2*dot(i,j). Selection: one warp per row.
template<int C0, int C1, bool INIT>
__global__ __launch_bounds__(256, 3) void k_dist_topk(){
    extern __shared__ float sh[];
    float* key = sh;                 // 8*NP floats (64 KB)
    float* rfT = sh + 8*NP;          // (C1-C0)*8 floats, [c][i]
    const int b  = blockIdx.y;
    const int i0 = blockIdx.x * 8;
    const int tid = threadIdx.x;
    constexpr int CD = C1 - C0;

    for (int idx = tid; idx < 8*CD; idx += 256)
        rfT[idx] = g_feat[(b*NP + i0 + (idx & 7))*CF + C0 + (idx >> 3)];
    __syncthreads();

    const float* fT = g_featT + b*CF*NP + C0*NP;
    #pragma unroll 1
    for (int pass = 0; pass < 2; ++pass){
        const int j0 = pass*1024 + tid*4;
        ull acc[8][2];
        if (INIT){
            #pragma unroll
            for (int i = 0; i < 8; i++){ acc[i][0] = 0ull; acc[i][1] = 0ull; }
        } else {
            #pragma unroll
            for (int i = 0; i < 8; i++){
                float4 d = __ldg((const float4*)(g_dot + (ull)(b*NP + i0 + i)*NP + j0));
                acc[i][0] = pack2(d.x, d.y); acc[i][1] = pack2(d.z, d.w);
            }
        }
        #pragma unroll 4
        for (int c = 0; c < CD; ++c){
            float4 v = __ldg((const float4*)(fT + c*NP + j0));
            ull v01 = pack2(v.x, v.y), v23 = pack2(v.z, v.w);
            const float4* r4 = (const float4*)(rfT + c*8);
            #pragma unroll
            for (int q = 0; q < 2; ++q){
                float4 r = r4[q];
                ull t;
                t = pack2(r.x, r.x); fma2(acc[q*4+0][0], t, v01); fma2(acc[q*4+0][1], t, v23);
                t = pack2(r.y, r.y); fma2(acc[q*4+1][0], t, v01); fma2(acc[q*4+1][1], t, v23);
                t = pack2(r.z, r.z); fma2(acc[q*4+2][0], t, v01); fma2(acc[q*4+2][1], t, v23);
                t = pack2(r.w, r.w); fma2(acc[q*4+3][0], t, v01); fma2(acc[q*4+3][1], t, v23);
            }
        }
        float4 sq4 = __ldg((const float4*)(g_sq + b*NP + j0));
        #pragma unroll
        for (int i = 0; i < 8; i++){
            float a0,a1,a2,a3;
            unpack2(acc[i][0], a0, a1); unpack2(acc[i][1], a2, a3);
            if (C1 < CF){   // last stage never re-read -> skip store
                float4 d; d.x = a0; d.y = a1; d.z = a2; d.w = a3;
                *(float4*)(g_dot + (ull)(b*NP + i0 + i)*NP + j0) = d;
            }
            float4 o;
            o.x = fmaf(-2.f, a0, sq4.x);
            o.y = fmaf(-2.f, a1, sq4.y);
            o.z = fmaf(-2.f, a2, sq4.z);
            o.w = fmaf(-2.f, a3, sq4.w);
            *(float4*)(key + i*NP + j0) = o;
        }
    }
    __syncthreads();

    // ---- selection: warp w handles row w
    const int w = tid >> 5, L = tid & 31;
    float* krow = key + w*NP;
    float cm0 = FINF, cm1 = FINF;
    {
        const float4* c4 = (const float4*)(krow + L*32);
        const float4* d4 = (const float4*)(krow + (L + 32)*32);
        #pragma unroll
        for (int t = 0; t < 8; ++t){
            int tt = (t + L) & 7;
            float4 u = c4[tt];
            cm0 = fminf(cm0, fminf(fminf(u.x, u.y), fminf(u.z, u.w)));
            float4 v = d4[tt];
            cm1 = fminf(cm1, fminf(fminf(v.x, v.y), fminf(v.z, v.w)));
        }
    }
    int* knnp = g_knn + (b*NP + i0 + w)*KNN;
    for (int it = 0; it < KNN; ++it){
        float m = fminf(cm0, cm1);
        #pragma unroll
        for (int off = 16; off; off >>= 1)
            m = fminf(m, __shfl_xor_sync(0xffffffffu, m, off));
        unsigned e0 = __ballot_sync(0xffffffffu, cm0 == m);
        unsigned e1 = __ballot_sync(0xffffffffu, cm1 == m);
        int ch = e0 ? (__ffs(e0) - 1) : (32 + __ffs(e1) - 1);
        float v = krow[ch*32 + L];
        unsigned eq = __ballot_sync(0xffffffffu, v == m);
        int jl = __ffs(eq) - 1;
        int j = ch*32 + jl;
        if (L == jl){ krow[j] = FINF; v = FINF; }
        if (L == 0) knnp[it] = j;
        float nm = v;
        #pragma unroll
        for (int off = 16; off; off >>= 1)
            nm = fminf(nm, __shfl_xor_sync(0xffffffffu, nm, off));
        if (L == (ch & 31)){
            if (ch < 32) cm0 = nm; else cm1 = nm;
        }
    }
}

// ---------------- per-point projections A = f*Wd^T, B2 = f*Wc^T -----------
// 16 points per block, COUT threads, c-outer loop, packed FFMA2.
template<int CIN, int COUT>
__global__ void k_proj(const float* __restrict__ W){
    __shared__ float cfT[CIN*16];                 // [c][p]
    int pbase = blockIdx.x * 16;
    int tid = threadIdx.x;                        // = out channel
    for (int idx = tid; idx < 16*CIN; idx += COUT)
        cfT[idx] = g_feat[(pbase + (idx & 15))*CF + (idx >> 4)];
    __syncthreads();
    const float* Wd = W + tid*2*CIN;
    const float* Wc = Wd + CIN;
    ull acca[8], accb[8];
    #pragma unroll
    for (int q = 0; q < 8; q++){ acca[q] = 0ull; accb[q] = 0ull; }
    #pragma unroll 4
    for (int c = 0; c < CIN; ++c){
        float wd = __ldg(Wd + c), wc = __ldg(Wc + c);
        ull wdp = pack2(wd, wd), wcp = pack2(wc, wc);
        const float4* p4 = (const float4*)(cfT + c*16);
        #pragma unroll
        for (int q = 0; q < 4; ++q){
            float4 pv = p4[q];
            ull p01 = pack2(pv.x, pv.y), p23 = pack2(pv.z, pv.w);
            fma2(acca[q*2  ], wdp, p01); fma2(acca[q*2+1], wdp, p23);
            fma2(accb[q*2  ], wcp, p01); fma2(accb[q*2+1], wcp, p23);
        }
    }
    #pragma unroll
    for (int q = 0; q < 8; ++q){
        float a0, a1, b0, b1;
        unpack2(acca[q], a0, a1); unpack2(accb[q], b0, b1);
        int p = q*2;
        g_A [(pbase + p    )*COUT + tid] = a0;
        g_A [(pbase + p + 1)*COUT + tid] = a1;
        g_B2[(pbase + p    )*COUT + tid] = b0;
        g_B2[(pbase + p + 1)*COUT + tid] = b1;
    }
}

// ---------------- gather neighbors + affine + leaky + max over k ----------
// 4 points per block.
template<int COUT>
__global__ void k_edge_max(const float* __restrict__ sv, const float* __restrict__ bv,
                           int offout){
    __shared__ int idxs[4*KNN];
    int P0 = blockIdx.x*4;
    int t = threadIdx.x;
    if (t < 4*KNN) idxs[t] = g_knn[P0*KNN + t];
    __syncthreads();
    int p = t / COUT, o = t - p*COUT;
    int P = P0 + p;
    int b = P >> 11, n = P & (NP-1);
    float Ai = g_A[P*COUT + o];
    float Bi = g_B2[P*COUT + o];
    float base = Bi - Ai;
    float hmax = -3.4e38f, hmin = 3.4e38f;
    const int* ip = idxs + p*KNN;
    #pragma unroll
    for (int k = 0; k < KNN; k++){
        float v = g_A[(b*NP + ip[k])*COUT + o] + base;
        hmax = fmaxf(hmax, v); hmin = fminf(hmin, v);
    }
    float s = sv[o], bb = bv[o];
    float y = fmaxf(lrelu(fmaf(s, hmax, bb)), lrelu(fmaf(s, hmin, bb)));
    g_feat[P*CF + offout + o] = y;
    g_featT[(b*CF + offout + o)*NP + n] = y;
}

// ---------------- W5 transpose for coalesced loads ------------------------
__global__ void k_w5t(const float* __restrict__ W5){
    int idx = blockIdx.x*256 + threadIdx.x;
    if (idx < 1024*323){
        int o = idx / 323, c = idx - o*323;
        g_W5T[c*1024 + o] = W5[idx];
    }
}

// ---------------- global 1024-ch conv + max-pool over N -------------------
// 32 points x 512 outs per block; thread = 32 points x 2 outs, packed FFMA2.
__global__ __launch_bounds__(256) void k_glob(const float* __restrict__ s5,
                                              const float* __restrict__ b5){
    __shared__ float cfT[CF*32];                  // [c][p], 41.3 KB
    int b = blockIdx.z;
    int p0 = blockIdx.x*32;
    for (int idx = threadIdx.x; idx < 32*CF; idx += 256){
        int p = idx / CF, c = idx - p*CF;
        cfT[c*32 + p] = g_feat[(b*NP + p0 + p)*CF + c];
    }
    __syncthreads();
    int o = blockIdx.y*512 + threadIdx.x*2;
    ull acc0[16], acc1[16];
    #pragma unroll
    for (int q = 0; q < 16; q++){ acc0[q] = 0ull; acc1[q] = 0ull; }
    const float* Wc = g_W5T + o;
    #pragma unroll 2
    for (int c = 0; c < CF; ++c){
        float2 wv = __ldg((const float2*)(Wc + c*1024));
        ull w0 = pack2(wv.x, wv.x), w1 = pack2(wv.y, wv.y);
        const float4* p4 = (const float4*)(cfT + c*32);
        #pragma unroll
        for (int q = 0; q < 8; ++q){
            float4 pv = p4[q];
            ull p01 = pack2(pv.x, pv.y), p23 = pack2(pv.z, pv.w);
            fma2(acc0[q*2  ], w0, p01); fma2(acc0[q*2+1], w0, p23);
            fma2(acc1[q*2  ], w1, p01); fma2(acc1[q*2+1], w1, p23);
        }
    }
    #pragma unroll
    for (int k = 0; k < 2; ++k){
        ull* a = k ? acc1 : acc0;
        float hmax = -3.4e38f, hmin = 3.4e38f;
        #pragma unroll
        for (int q = 0; q < 16; ++q){
            float x0, x1; unpack2(a[q], x0, x1);
            hmax = fmaxf(hmax, fmaxf(x0, x1));
            hmin = fminf(hmin, fminf(x0, x1));
        }
        float s = s5[o + k], bb = b5[o + k];
        float y = fmaxf(lrelu(fmaf(s, hmax, bb)), lrelu(fmaf(s, hmin, bb)));
        atomicMax(&g_gmax[b*1024 + o + k], enc_f(y));
    }
}

// ---------------- decode maxpool, emit gfeat ------------------------------
__global__ void k_finalize(float* __restrict__ out){
    int i = blockIdx.x*256 + threadIdx.x;        // NB*1024 threads
    float f = dec_f(g_gmax[i]);
    g_gfeat[i] = f;
    out[NB*40 + i] = f;                           // gfeat after logits
}

// ---------------- FC head -------------------------------------------------
__global__ void k_fc(const float* __restrict__ W, const float* __restrict__ bias,
                     const float* __restrict__ sv, const float* __restrict__ Bv,
                     float* __restrict__ dout, int indim, int outdim, int layer){
    __shared__ float vin[1024];
    int b = blockIdx.x;
    const float* in = (layer == 1) ? (g_gfeat + b*1024)
                    : (layer == 2) ? (g_h1 + b*512) : (g_h2 + b*256);
    float* outp = (layer == 1) ? (g_h1 + b*512)
                : (layer == 2) ? (g_h2 + b*256) : (dout + b*40);
    for (int idx = threadIdx.x; idx < indim; idx += blockDim.x) vin[idx] = in[idx];
    __syncthreads();
    for (int o = threadIdx.x; o < outdim; o += blockDim.x){
        float a = 0.f;
        const float* Wr = W + o*indim;
        #pragma unroll 4
        for (int c = 0; c < indim; c++) a = fmaf(__ldg(Wr + c), vin[c], a);
        a += bias[o];
        if (layer != 3){
            a = fmaf(a, sv[o], Bv[o]);
            a = lrelu(a);
        }
        outp[o] = a;
    }
}

// ---------------- launch --------------------------------------------------
extern "C" void kernel_launch(void* const* d_in, const int* in_sizes, int n_in,
                              void* d_out, int out_size){
    const float* x   = (const float*)d_in[0];
    const float* W1  = (const float*)d_in[1];
    const float* s1  = (const float*)d_in[2];
    const float* b1  = (const float*)d_in[3];
    const float* W2  = (const float*)d_in[4];
    const float* s2  = (const float*)d_in[5];
    const float* b2  = (const float*)d_in[6];
    const float* W3  = (const float*)d_in[7];
    const float* s3  = (const float*)d_in[8];
    const float* b3  = (const float*)d_in[9];
    const float* W4  = (const float*)d_in[10];
    const float* s4  = (const float*)d_in[11];
    const float* b4  = (const float*)d_in[12];
    const float* W5  = (const float*)d_in[13];
    const float* s5  = (const float*)d_in[14];
    const float* b5  = (const float*)d_in[15];
    const float* fW1 = (const float*)d_in[16];
    const float* fb1 = (const float*)d_in[17];
    const float* fs1 = (const float*)d_in[18];
    const float* fB1 = (const float*)d_in[19];
    const float* fW2 = (const float*)d_in[20];
    const float* fb2 = (const float*)d_in[21];
    const float* fs2 = (const float*)d_in[22];
    const float* fB2 = (const float*)d_in[23];
    const float* fW3 = (const float*)d_in[24];
    const float* fb3 = (const float*)d_in[25];
    float* out = (float*)d_out;

    const int smA = (8*NP + 8*3 ) * 4;
    const int smB = (8*NP + 8*64) * 4;
    cudaFuncSetAttribute((const void*)k_dist_topk<0,3,true>,
                         cudaFuncAttributeMaxDynamicSharedMemorySize, smA);
    cudaFuncSetAttribute((const void*)k_dist_topk<3,67,false>,
                         cudaFuncAttributeMaxDynamicSharedMemorySize, smB);
    cudaFuncSetAttribute((const void*)k_dist_topk<67,131,false>,
                         cudaFuncAttributeMaxDynamicSharedMemorySize, smB);
    cudaFuncSetAttribute((const void*)k_dist_topk<131,195,false>,
                         cudaFuncAttributeMaxDynamicSharedMemorySize, smB);

    k_init<<<NB*NP/256, 256>>>(x);
    k_initmax<<<(NB*1024 + 255)/256, 256>>>();

    // ---- EdgeConv stage 1: Cin=3, Cout=64, out offset 3
    k_sq_add<<<NB*NP/256, 256>>>(0, 3, 1);
    k_dist_topk<0,3,true><<<dim3(NP/8, NB), 256, smA>>>();
    k_proj<3,64><<<NB*NP/16, 64>>>(W1);
    k_edge_max<64><<<NB*NP/4, 256>>>(s1, b1, 3);

    // ---- EdgeConv stage 2: Cin=67, Cout=64, out offset 67
    k_sq_add<<<NB*NP/256, 256>>>(3, 67, 0);
    k_dist_topk<3,67,false><<<dim3(NP/8, NB), 256, smB>>>();
    k_proj<67,64><<<NB*NP/16, 64>>>(W2);
    k_edge_max<64><<<NB*NP/4, 256>>>(s2, b2, 67);

    // ---- EdgeConv stage 3: Cin=131, Cout=64, out offset 131
    k_sq_add<<<NB*NP/256, 256>>>(67, 131, 0);
    k_dist_topk<67,131,false><<<dim3(NP/8, NB), 256, smB>>>();
    k_proj<131,64><<<NB*NP/16, 64>>>(W3);
    k_edge_max<64><<<NB*NP/4, 256>>>(s3, b3, 131);

    // ---- EdgeConv stage 4: Cin=195, Cout=128, out offset 195
    k_sq_add<<<NB*NP/256, 256>>>(131, 195, 0);
    k_dist_topk<131,195,false><<<dim3(NP/8, NB), 256, smB>>>();
    k_proj<195,128><<<NB*NP/16, 128>>>(W4);
    k_edge_max<128><<<NB*NP/4, 512>>>(s4, b4, 195);

    // ---- Global conv (1024) + maxpool over N
    k_w5t<<<(1024*323 + 255)/256, 256>>>(W5);
    k_glob<<<dim3(NP/32, 2, NB), 256>>>(s5, b5);
    k_finalize<<<NB*1024/256, 256>>>(out);

    // ---- FC head
    k_fc<<<NB, 256>>>(fW1, fb1, fs1, fB1, out, 1024, 512, 1);
    k_fc<<<NB, 256>>>(fW2, fb2, fs2, fB2, out,  512, 256, 2);
    k_fc<<<NB, 256>>>(fW3, fb3, fs1, fB1, out,  256,  40, 3);
}

// round 5
// speedup vs baseline: 4.6618x; 1.0033x over previous
#include <cuda_runtime.h>

#define NB 8
#define NP 2048
#define KNN 20
#define CF 323
#define NEG 0.2f
#define FINF __int_as_float(0x7f800000)

typedef unsigned long long ull;

// ---------------- scratch (device globals; no allocations) ----------------
__device__ float g_feat[NB*NP*CF];      // [b][n][c] : pts|f1|f2|f3|f4
__device__ float g_featT[NB*CF*NP];     // [b][c][n]
__device__ float g_sq[NB*NP];
__device__ int   g_knn[NB*NP*KNN];
__device__ float g_A[NB*NP*128];        // feat @ Wd^T
__device__ float g_B2[NB*NP*128];       // feat @ Wc^T
__device__ float g_dot[NB*NP*NP];       // running pairwise dot products (134 MB)
__device__ float g_WT[2*195*128];       // per-stage transposed W: [c][2*COUT]
__device__ float g_W5T[323*1024];
__device__ unsigned int g_gmax[NB*1024];
__device__ float g_gfeat[NB*1024];
__device__ float g_h1[NB*512];
__device__ float g_h2[NB*256];

__device__ __forceinline__ unsigned enc_f(float f){
    unsigned u = __float_as_uint(f);
    return (u & 0x80000000u) ? ~u : (u | 0x80000000u);
}
__device__ __forceinline__ float dec_f(unsigned u){
    return (u & 0x80000000u) ? __uint_as_float(u ^ 0x80000000u) : __uint_as_float(~u);
}
__device__ __forceinline__ float lrelu(float z){ return z > 0.f ? z : NEG*z; }

// packed f32x2 helpers (sm_103a FFMA2)
__device__ __forceinline__ ull pack2(float lo, float hi){
    ull r; asm("mov.b64 %0, {%1, %2};" : "=l"(r)
               : "r"(__float_as_uint(lo)), "r"(__float_as_uint(hi)));
    return r;
}
__device__ __forceinline__ void unpack2(ull v, float& lo, float& hi){
    unsigned a, b; asm("mov.b64 {%0, %1}, %2;" : "=r"(a), "=r"(b) : "l"(v));
    lo = __uint_as_float(a); hi = __uint_as_float(b);
}
__device__ __forceinline__ void fma2(ull& d, ull a, ull b){
    asm("fma.rn.f32x2 %0, %1, %2, %0;" : "+l"(d) : "l"(a), "l"(b));
}

// ---------------- init: transpose x into feat/featT, reset maxpool --------
__global__ void k_init(const float* __restrict__ x){
    int idx = blockIdx.x*256 + threadIdx.x;       // NB*NP threads
    int b = idx >> 11, n = idx & (NP-1);
    #pragma unroll
    for (int c = 0; c < 3; c++){
        float v = x[(b*3 + c)*NP + n];
        g_feat[idx*CF + c] = v;
        g_featT[(b*CF + c)*NP + n] = v;
    }
}

__global__ void k_initmax(){
    int idx = blockIdx.x*256 + threadIdx.x;
    if (idx < NB*1024) g_gmax[idx] = 0u;
}

// ---------------- squared norms: incremental over new channel block -------
__global__ void k_sq_add(int c0, int c1, int init){
    int idx = blockIdx.x*256 + threadIdx.x;       // NB*NP threads
    int b = idx >> 11, n = idx & (NP-1);
    const float* fT = g_featT + (b*CF)*NP + n;
    float s = init ? 0.f : g_sq[idx];
    for (int c = c0; c < c1; c++){ float v = fT[c*NP]; s = fmaf(v, v, s); }
    g_sq[idx] = s;
}

// ---------------- fused incremental-dot GEMM + top-20 selection -----------
// Block = 8 query rows x 2048 cols (64KB key -> 3 CTAs/SM).
// acc layout: [row-pair][col]; row pairs loaded as packed u64 from rfT,
// column value duplicated. key[i][j] = sq_j - 2*dot(i,j).
template<int C0, int C1, bool INIT, bool STORE>
__global__ __launch_bounds__(256, 3) void k_dist_topk(){
    extern __shared__ float sh[];
    float* key = sh;                 // 8*NP floats (64 KB)
    float* rfT = sh + 8*NP;          // (C1-C0)*8 floats, [c][row]
    const int b  = blockIdx.y;
    const int i0 = blockIdx.x * 8;
    const int tid = threadIdx.x;
    constexpr int CD = C1 - C0;

    for (int idx = tid; idx < 8*CD; idx += 256)
        rfT[idx] = g_feat[(b*NP + i0 + (idx & 7))*CF + C0 + (idx >> 3)];
    __syncthreads();

    const float* fT = g_featT + b*CF*NP + C0*NP;
    #pragma unroll 1
    for (int pass = 0; pass < 2; ++pass){
        const int j0 = pass*1024 + tid*4;
        ull acc[4][4];               // [pair p: rows 2p,2p+1][col q]
        if (INIT){
            #pragma unroll
            for (int p = 0; p < 4; p++)
                #pragma unroll
                for (int q = 0; q < 4; q++) acc[p][q] = 0ull;
        } else {
            #pragma unroll
            for (int p = 0; p < 4; p++){
                float4 d0 = __ldg((const float4*)(g_dot + (ull)(b*NP + i0 + 2*p    )*NP + j0));
                float4 d1 = __ldg((const float4*)(g_dot + (ull)(b*NP + i0 + 2*p + 1)*NP + j0));
                acc[p][0] = pack2(d0.x, d1.x); acc[p][1] = pack2(d0.y, d1.y);
                acc[p][2] = pack2(d0.z, d1.z); acc[p][3] = pack2(d0.w, d1.w);
            }
        }
        #pragma unroll 4
        for (int c = 0; c < CD; ++c){
            float4 v = __ldg((const float4*)(fT + c*NP + j0));
            ull vc0 = pack2(v.x, v.x), vc1 = pack2(v.y, v.y);
            ull vc2 = pack2(v.z, v.z), vc3 = pack2(v.w, v.w);
            const ull* rp = (const ull*)(rfT + c*8);
            #pragma unroll
            for (int p = 0; p < 4; ++p){
                ull r = rp[p];
                fma2(acc[p][0], r, vc0); fma2(acc[p][1], r, vc1);
                fma2(acc[p][2], r, vc2); fma2(acc[p][3], r, vc3);
            }
        }
        float4 sq4 = __ldg((const float4*)(g_sq + b*NP + j0));
        #pragma unroll
        for (int p = 0; p < 4; ++p){
            float4 dlo, dhi;
            unpack2(acc[p][0], dlo.x, dhi.x); unpack2(acc[p][1], dlo.y, dhi.y);
            unpack2(acc[p][2], dlo.z, dhi.z); unpack2(acc[p][3], dlo.w, dhi.w);
            if (STORE){
                *(float4*)(g_dot + (ull)(b*NP + i0 + 2*p    )*NP + j0) = dlo;
                *(float4*)(g_dot + (ull)(b*NP + i0 + 2*p + 1)*NP + j0) = dhi;
            }
            float4 o0, o1;
            o0.x = fmaf(-2.f, dlo.x, sq4.x); o0.y = fmaf(-2.f, dlo.y, sq4.y);
            o0.z = fmaf(-2.f, dlo.z, sq4.z); o0.w = fmaf(-2.f, dlo.w, sq4.w);
            o1.x = fmaf(-2.f, dhi.x, sq4.x); o1.y = fmaf(-2.f, dhi.y, sq4.y);
            o1.z = fmaf(-2.f, dhi.z, sq4.z); o1.w = fmaf(-2.f, dhi.w, sq4.w);
            *(float4*)(key + (2*p    )*NP + j0) = o0;
            *(float4*)(key + (2*p + 1)*NP + j0) = o1;
        }
    }
    __syncthreads();

    // ---- selection: warp w handles row w
    const int w = tid >> 5, L = tid & 31;
    float* krow = key + w*NP;
    float cm0 = FINF, cm1 = FINF;
    {
        const float4* c4 = (const float4*)(krow + L*32);
        const float4* d4 = (const float4*)(krow + (L + 32)*32);
        #pragma unroll
        for (int t = 0; t < 8; ++t){
            int tt = (t + L) & 7;
            float4 u = c4[tt];
            cm0 = fminf(cm0, fminf(fminf(u.x, u.y), fminf(u.z, u.w)));
            float4 v = d4[tt];
            cm1 = fminf(cm1, fminf(fminf(v.x, v.y), fminf(v.z, v.w)));
        }
    }
    int* knnp = g_knn + (b*NP + i0 + w)*KNN;
    for (int it = 0; it < KNN; ++it){
        float m = fminf(cm0, cm1);
        #pragma unroll
        for (int off = 16; off; off >>= 1)
            m = fminf(m, __shfl_xor_sync(0xffffffffu, m, off));
        unsigned e0 = __ballot_sync(0xffffffffu, cm0 == m);
        unsigned e1 = __ballot_sync(0xffffffffu, cm1 == m);
        int ch = e0 ? (__ffs(e0) - 1) : (32 + __ffs(e1) - 1);
        float v = krow[ch*32 + L];
        unsigned eq = __ballot_sync(0xffffffffu, v == m);
        int jl = __ffs(eq) - 1;
        int j = ch*32 + jl;
        if (L == jl){ krow[j] = FINF; v = FINF; }
        if (L == 0) knnp[it] = j;
        float nm = v;
        #pragma unroll
        for (int off = 16; off; off >>= 1)
            nm = fminf(nm, __shfl_xor_sync(0xffffffffu, nm, off));
        if (L == (ch & 31)){
            if (ch < 32) cm0 = nm; else cm1 = nm;
        }
    }
}

// ---------------- W transpose: W[o][half*CIN+c] -> WT[c][half*COUT+o] -----
__global__ void k_wt(const float* __restrict__ W, int CIN, int COUT){
    int idx = blockIdx.x*256 + threadIdx.x;
    int tot = 2*CIN*COUT;
    if (idx >= tot) return;
    int c = idx % CIN; int rest = idx / CIN;
    int o = rest % COUT; int half = rest / COUT;
    g_WT[c*(2*COUT) + half*COUT + o] = W[o*2*CIN + half*CIN + c];
}

// ---------------- tiled projection GEMM: [32 pts] x [2*COUT] x CIN --------
// Thread = (u, g): out-channel u, point-group g. Points pair-packed for FFMA2.
template<int CIN, int COUT>
__global__ __launch_bounds__(256) void k_proj2(){
    constexpr int OD = 2*COUT;          // 128 or 256
    constexpr int NG = 256/OD;          // groups (2 or 1)
    constexpr int PT = 32/NG;           // points per thread (16 or 32)
    constexpr int CCH = 16;
    __shared__ __align__(16) float ptsT[CIN*32];
    __shared__ __align__(16) float wt[CCH*OD];
    int pbase = blockIdx.x * 32;
    int tid = threadIdx.x;
    int u = tid & (OD-1), g = tid / OD;

    for (int idx = tid; idx < 32*CIN; idx += 256){
        int p = idx / CIN, c = idx - p*CIN;
        ptsT[c*32 + p] = g_feat[(pbase + p)*CF + c];
    }

    ull acc[PT/2];
    #pragma unroll
    for (int t = 0; t < PT/2; t++) acc[t] = 0ull;

    for (int c0 = 0; c0 < CIN; c0 += CCH){
        __syncthreads();
        for (int idx = tid; idx < CCH*OD; idx += 256){
            int cc = idx / OD;
            if (c0 + cc < CIN) wt[idx] = g_WT[(c0 + cc)*OD + (idx & (OD-1))];
        }
        __syncthreads();
        int cend = (CIN - c0 < CCH) ? (CIN - c0) : CCH;
        for (int cc = 0; cc < cend; ++cc){
            float w = wt[cc*OD + u];
            ull wp = pack2(w, w);
            const ull* pp = (const ull*)(ptsT + (c0 + cc)*32) + g*(PT/2);
            #pragma unroll
            for (int t = 0; t < PT/2; ++t) fma2(acc[t], wp, pp[t]);
        }
    }

    int o = (u < COUT) ? u : (u - COUT);
    float* dst = (u < COUT) ? g_A : g_B2;
    #pragma unroll
    for (int t = 0; t < PT/2; ++t){
        float v0, v1; unpack2(acc[t], v0, v1);
        int p = pbase + g*PT + 2*t;
        dst[(p    )*COUT + o] = v0;
        dst[(p + 1)*COUT + o] = v1;
    }
}

// ---------------- gather neighbors + affine + leaky + max over k ----------
// 4 points per block.
template<int COUT>
__global__ void k_edge_max(const float* __restrict__ sv, const float* __restrict__ bv,
                           int offout){
    __shared__ int idxs[4*KNN];
    int P0 = blockIdx.x*4;
    int t = threadIdx.x;
    if (t < 4*KNN) idxs[t] = g_knn[P0*KNN + t];
    __syncthreads();
    int p = t / COUT, o = t - p*COUT;
    int P = P0 + p;
    int b = P >> 11, n = P & (NP-1);
    float Ai = g_A[P*COUT + o];
    float Bi = g_B2[P*COUT + o];
    float base = Bi - Ai;
    float hmax = -3.4e38f, hmin = 3.4e38f;
    const int* ip = idxs + p*KNN;
    #pragma unroll
    for (int k = 0; k < KNN; k++){
        float v = g_A[(b*NP + ip[k])*COUT + o] + base;
        hmax = fmaxf(hmax, v); hmin = fminf(hmin, v);
    }
    float s = sv[o], bb = bv[o];
    float y = fmaxf(lrelu(fmaf(s, hmax, bb)), lrelu(fmaf(s, hmin, bb)));
    g_feat[P*CF + offout + o] = y;
    g_featT[(b*CF + offout + o)*NP + n] = y;
}

// ---------------- W5 transpose for coalesced loads ------------------------
__global__ void k_w5t(const float* __restrict__ W5){
    int idx = blockIdx.x*256 + threadIdx.x;
    if (idx < 1024*323){
        int o = idx / 323, c = idx - o*323;
        g_W5T[c*1024 + o] = W5[idx];
    }
}

// ---------------- global 1024-ch conv + max-pool over N -------------------
// 32 points x 512 outs per block; thread = 32 points x 2 outs, packed FFMA2.
__global__ __launch_bounds__(256) void k_glob(const float* __restrict__ s5,
                                              const float* __restrict__ b5){
    __shared__ float cfT[CF*32];                  // [c][p], 41.3 KB
    int b = blockIdx.z;
    int p0 = blockIdx.x*32;
    for (int idx = threadIdx.x; idx < 32*CF; idx += 256){
        int p = idx / CF, c = idx - p*CF;
        cfT[c*32 + p] = g_feat[(b*NP + p0 + p)*CF + c];
    }
    __syncthreads();
    int o = blockIdx.y*512 + threadIdx.x*2;
    ull acc0[16], acc1[16];
    #pragma unroll
    for (int q = 0; q < 16; q++){ acc0[q] = 0ull; acc1[q] = 0ull; }
    const float* Wc = g_W5T + o;
    #pragma unroll 2
    for (int c = 0; c < CF; ++c){
        float2 wv = __ldg((const float2*)(Wc + c*1024));
        ull w0 = pack2(wv.x, wv.x), w1 = pack2(wv.y, wv.y);
        const float4* p4 = (const float4*)(cfT + c*32);
        #pragma unroll
        for (int q = 0; q < 8; ++q){
            float4 pv = p4[q];
            ull p01 = pack2(pv.x, pv.y), p23 = pack2(pv.z, pv.w);
            fma2(acc0[q*2  ], w0, p01); fma2(acc0[q*2+1], w0, p23);
            fma2(acc1[q*2  ], w1, p01); fma2(acc1[q*2+1], w1, p23);
        }
    }
    #pragma unroll
    for (int k = 0; k < 2; ++k){
        ull* a = k ? acc1 : acc0;
        float hmax = -3.4e38f, hmin = 3.4e38f;
        #pragma unroll
        for (int q = 0; q < 16; ++q){
            float x0, x1; unpack2(a[q], x0, x1);
            hmax = fmaxf(hmax, fmaxf(x0, x1));
            hmin = fminf(hmin, fminf(x0, x1));
        }
        float s = s5[o + k], bb = b5[o + k];
        float y = fmaxf(lrelu(fmaf(s, hmax, bb)), lrelu(fmaf(s, hmin, bb)));
        atomicMax(&g_gmax[b*1024 + o + k], enc_f(y));
    }
}

// ---------------- decode maxpool, emit gfeat ------------------------------
__global__ void k_finalize(float* __restrict__ out){
    int i = blockIdx.x*256 + threadIdx.x;        // NB*1024 threads
    float f = dec_f(g_gmax[i]);
    g_gfeat[i] = f;
    out[NB*40 + i] = f;                           // gfeat after logits
}

// ---------------- FC head -------------------------------------------------
__global__ void k_fc(const float* __restrict__ W, const float* __restrict__ bias,
                     const float* __restrict__ sv, const float* __restrict__ Bv,
                     float* __restrict__ dout, int indim, int outdim, int layer){
    __shared__ float vin[1024];
    int b = blockIdx.x;
    const float* in = (layer == 1) ? (g_gfeat + b*1024)
                    : (layer == 2) ? (g_h1 + b*512) : (g_h2 + b*256);
    float* outp = (layer == 1) ? (g_h1 + b*512)
                : (layer == 2) ? (g_h2 + b*256) : (dout + b*40);
    for (int idx = threadIdx.x; idx < indim; idx += blockDim.x) vin[idx] = in[idx];
    __syncthreads();
    for (int o = threadIdx.x; o < outdim; o += blockDim.x){
        float a = 0.f;
        const float* Wr = W + o*indim;
        #pragma unroll 4
        for (int c = 0; c < indim; c++) a = fmaf(__ldg(Wr + c), vin[c], a);
        a += bias[o];
        if (layer != 3){
            a = fmaf(a, sv[o], Bv[o]);
            a = lrelu(a);
        }
        outp[o] = a;
    }
}

// ---------------- launch --------------------------------------------------
extern "C" void kernel_launch(void* const* d_in, const int* in_sizes, int n_in,
                              void* d_out, int out_size){
    const float* x   = (const float*)d_in[0];
    const float* W1  = (const float*)d_in[1];
    const float* s1  = (const float*)d_in[2];
    const float* b1  = (const float*)d_in[3];
    const float* W2  = (const float*)d_in[4];
    const float* s2  = (const float*)d_in[5];
    const float* b2  = (const float*)d_in[6];
    const float* W3  = (const float*)d_in[7];
    const float* s3  = (const float*)d_in[8];
    const float* b3  = (const float*)d_in[9];
    const float* W4  = (const float*)d_in[10];
    const float* s4  = (const float*)d_in[11];
    const float* b4  = (const float*)d_in[12];
    const float* W5  = (const float*)d_in[13];
    const float* s5  = (const float*)d_in[14];
    const float* b5  = (const float*)d_in[15];
    const float* fW1 = (const float*)d_in[16];
    const float* fb1 = (const float*)d_in[17];
    const float* fs1 = (const float*)d_in[18];
    const float* fB1 = (const float*)d_in[19];
    const float* fW2 = (const float*)d_in[20];
    const float* fb2 = (const float*)d_in[21];
    const float* fs2 = (const float*)d_in[22];
    const float* fB2 = (const float*)d_in[23];
    const float* fW3 = (const float*)d_in[24];
    const float* fb3 = (const float*)d_in[25];
    float* out = (float*)d_out;

    const int sm1 = (8*NP + 8*3 ) * 4;
    const int sm2 = (8*NP + 8*67) * 4;
    const int smB = (8*NP + 8*64) * 4;
    cudaFuncSetAttribute((const void*)k_dist_topk<0,3,true,false>,
                         cudaFuncAttributeMaxDynamicSharedMemorySize, sm1);
    cudaFuncSetAttribute((const void*)k_dist_topk<0,67,true,true>,
                         cudaFuncAttributeMaxDynamicSharedMemorySize, sm2);
    cudaFuncSetAttribute((const void*)k_dist_topk<67,131,false,true>,
                         cudaFuncAttributeMaxDynamicSharedMemorySize, smB);
    cudaFuncSetAttribute((const void*)k_dist_topk<131,195,false,false>,
                         cudaFuncAttributeMaxDynamicSharedMemorySize, smB);

    k_init<<<NB*NP/256, 256>>>(x);
    k_initmax<<<(NB*1024 + 255)/256, 256>>>();

    // ---- EdgeConv stage 1: Cin=3, Cout=64, out offset 3
    k_sq_add<<<NB*NP/256, 256>>>(0, 3, 1);
    k_dist_topk<0,3,true,false><<<dim3(NP/8, NB), 256, sm1>>>();
    k_wt<<<(2*3*64 + 255)/256, 256>>>(W1, 3, 64);
    k_proj2<3,64><<<NB*NP/32, 256>>>();
    k_edge_max<64><<<NB*NP/4, 256>>>(s1, b1, 3);

    // ---- EdgeConv stage 2: Cin=67, Cout=64, out offset 67
    k_sq_add<<<NB*NP/256, 256>>>(3, 67, 0);
    k_dist_topk<0,67,true,true><<<dim3(NP/8, NB), 256, sm2>>>();
    k_wt<<<(2*67*64 + 255)/256, 256>>>(W2, 67, 64);
    k_proj2<67,64><<<NB*NP/32, 256>>>();
    k_edge_max<64><<<NB*NP/4, 256>>>(s2, b2, 67);

    // ---- EdgeConv stage 3: Cin=131, Cout=64, out offset 131
    k_sq_add<<<NB*NP/256, 256>>>(67, 131, 0);
    k_dist_topk<67,131,false,true><<<dim3(NP/8, NB), 256, smB>>>();
    k_wt<<<(2*131*64 + 255)/256, 256>>>(W3, 131, 64);
    k_proj2<131,64><<<NB*NP/32, 256>>>();
    k_edge_max<64><<<NB*NP/4, 256>>>(s3, b3, 131);

    // ---- EdgeConv stage 4: Cin=195, Cout=128, out offset 195
    k_sq_add<<<NB*NP/256, 256>>>(131, 195, 0);
    k_dist_topk<131,195,false,false><<<dim3(NP/8, NB), 256, smB>>>();
    k_wt<<<(2*195*128 + 255)/256, 256>>>(W4, 195, 128);
    k_proj2<195,128><<<NB*NP/32, 256>>>();
    k_edge_max<128><<<NB*NP/4, 512>>>(s4, b4, 195);

    // ---- Global conv (1024) + maxpool over N
    k_w5t<<<(1024*323 + 255)/256, 256>>>(W5);
    k_glob<<<dim3(NP/32, 2, NB), 256>>>(s5, b5);
    k_finalize<<<NB*1024/256, 256>>>(out);

    // ---- FC head
    k_fc<<<NB, 256>>>(fW1, fb1, fs1, fB1, out, 1024, 512, 1);
    k_fc<<<NB, 256>>>(fW2, fb2, fs2, fB2, out,  512, 256, 2);
    k_fc<<<NB, 256>>>(fW3, fb3, fs1, fB1, out,  256,  40, 3);
}

// round 6
// speedup vs baseline: 5.9859x; 1.2840x over previous
#include <cuda_runtime.h>

#define NB 8
#define NP 2048
#define KNN 20
#define CF 323
#define NEG 0.2f
#define FINF __int_as_float(0x7f800000)

typedef unsigned long long ull;

// ---------------- scratch (device globals; no allocations) ----------------
__device__ float g_feat[NB*NP*CF];      // [b][n][c] : pts|f1|f2|f3|f4
__device__ float g_featT[NB*CF*NP];     // [b][c][n]
__device__ float g_sq[NB*NP];
__device__ int   g_knn[NB*NP*KNN];
__device__ float g_A[NB*NP*128];        // feat @ Wd^T
__device__ float g_B2[NB*NP*128];       // feat @ Wc^T
__device__ float g_dot[NB*NP*NP];       // running pairwise dot products (134 MB)
__device__ float g_WT[2*195*128];       // per-stage transposed W: [c][2*COUT]
__device__ float g_W5T[323*1024];
__device__ unsigned int g_gmax[NB*1024];
__device__ float g_gfeat[NB*1024];
__device__ float g_h1[NB*512];
__device__ float g_h2[NB*256];

__device__ __forceinline__ unsigned enc_f(float f){
    unsigned u = __float_as_uint(f);
    return (u & 0x80000000u) ? ~u : (u | 0x80000000u);
}
__device__ __forceinline__ float dec_f(unsigned u){
    return (u & 0x80000000u) ? __uint_as_float(u ^ 0x80000000u) : __uint_as_float(~u);
}
__device__ __forceinline__ float lrelu(float z){ return z > 0.f ? z : NEG*z; }

// packed f32x2 helpers (sm_103a FFMA2)
__device__ __forceinline__ ull pack2(float lo, float hi){
    ull r; asm("mov.b64 %0, {%1, %2};" : "=l"(r)
               : "r"(__float_as_uint(lo)), "r"(__float_as_uint(hi)));
    return r;
}
__device__ __forceinline__ void unpack2(ull v, float& lo, float& hi){
    unsigned a, b; asm("mov.b64 {%0, %1}, %2;" : "=r"(a), "=r"(b) : "l"(v));
    lo = __uint_as_float(a); hi = __uint_as_float(b);
}
__device__ __forceinline__ void fma2(ull& d, ull a, ull b){
    asm("fma.rn.f32x2 %0, %1, %2, %0;" : "+l"(d) : "l"(a), "l"(b));
}

// ---------------- init: transpose x into feat/featT, reset maxpool --------
__global__ void k_init(const float* __restrict__ x){
    int idx = blockIdx.x*256 + threadIdx.x;       // NB*NP threads
    int b = idx >> 11, n = idx & (NP-1);
    #pragma unroll
    for (int c = 0; c < 3; c++){
        float v = x[(b*3 + c)*NP + n];
        g_feat[idx*CF + c] = v;
        g_featT[(b*CF + c)*NP + n] = v;
    }
}

__global__ void k_initmax(){
    int idx = blockIdx.x*256 + threadIdx.x;
    if (idx < NB*1024) g_gmax[idx] = 0u;
}

// ---------------- squared norms: incremental, 4-way ILP -------------------
__global__ void k_sq_add(int c0, int c1, int init){
    int idx = blockIdx.x*256 + threadIdx.x;       // NB*NP threads
    int b = idx >> 11, n = idx & (NP-1);
    const float* fT = g_featT + (b*CF)*NP + n;
    float s0 = init ? 0.f : g_sq[idx], s1 = 0.f, s2 = 0.f, s3 = 0.f;
    int c = c0;
    for (; c + 4 <= c1; c += 4){
        float v0 = fT[(c    )*NP], v1 = fT[(c + 1)*NP];
        float v2 = fT[(c + 2)*NP], v3 = fT[(c + 3)*NP];
        s0 = fmaf(v0, v0, s0); s1 = fmaf(v1, v1, s1);
        s2 = fmaf(v2, v2, s2); s3 = fmaf(v3, v3, s3);
    }
    for (; c < c1; c++){ float v = fT[c*NP]; s0 = fmaf(v, v, s0); }
    g_sq[idx] = ((s0 + s1) + (s2 + s3));
}

// ---------------- fused incremental-dot GEMM + top-20 selection -----------
// Block = 8 query rows x 2048 cols (64KB key -> 3 CTAs/SM).
template<int C0, int C1, bool INIT, bool STORE>
__global__ __launch_bounds__(256, 3) void k_dist_topk(){
    extern __shared__ float sh[];
    float* key = sh;                 // 8*NP floats (64 KB)
    float* rfT = sh + 8*NP;          // (C1-C0)*8 floats, [c][row]
    const int b  = blockIdx.y;
    const int i0 = blockIdx.x * 8;
    const int tid = threadIdx.x;
    constexpr int CD = C1 - C0;

    for (int idx = tid; idx < 8*CD; idx += 256)
        rfT[idx] = g_feat[(b*NP + i0 + (idx & 7))*CF + C0 + (idx >> 3)];
    __syncthreads();

    const float* fT = g_featT + b*CF*NP + C0*NP;
    #pragma unroll 1
    for (int pass = 0; pass < 2; ++pass){
        const int j0 = pass*1024 + tid*4;
        ull acc[4][4];               // [pair p: rows 2p,2p+1][col q]
        if (INIT){
            #pragma unroll
            for (int p = 0; p < 4; p++)
                #pragma unroll
                for (int q = 0; q < 4; q++) acc[p][q] = 0ull;
        } else {
            #pragma unroll
            for (int p = 0; p < 4; p++){
                float4 d0 = __ldg((const float4*)(g_dot + (ull)(b*NP + i0 + 2*p    )*NP + j0));
                float4 d1 = __ldg((const float4*)(g_dot + (ull)(b*NP + i0 + 2*p + 1)*NP + j0));
                acc[p][0] = pack2(d0.x, d1.x); acc[p][1] = pack2(d0.y, d1.y);
                acc[p][2] = pack2(d0.z, d1.z); acc[p][3] = pack2(d0.w, d1.w);
            }
        }
        #pragma unroll 4
        for (int c = 0; c < CD; ++c){
            float4 v = __ldg((const float4*)(fT + c*NP + j0));
            ull vc0 = pack2(v.x, v.x), vc1 = pack2(v.y, v.y);
            ull vc2 = pack2(v.z, v.z), vc3 = pack2(v.w, v.w);
            const ull* rp = (const ull*)(rfT + c*8);
            #pragma unroll
            for (int p = 0; p < 4; ++p){
                ull r = rp[p];
                fma2(acc[p][0], r, vc0); fma2(acc[p][1], r, vc1);
                fma2(acc[p][2], r, vc2); fma2(acc[p][3], r, vc3);
            }
        }
        float4 sq4 = __ldg((const float4*)(g_sq + b*NP + j0));
        #pragma unroll
        for (int p = 0; p < 4; ++p){
            float4 dlo, dhi;
            unpack2(acc[p][0], dlo.x, dhi.x); unpack2(acc[p][1], dlo.y, dhi.y);
            unpack2(acc[p][2], dlo.z, dhi.z); unpack2(acc[p][3], dlo.w, dhi.w);
            if (STORE){
                *(float4*)(g_dot + (ull)(b*NP + i0 + 2*p    )*NP + j0) = dlo;
                *(float4*)(g_dot + (ull)(b*NP + i0 + 2*p + 1)*NP + j0) = dhi;
            }
            float4 o0, o1;
            o0.x = fmaf(-2.f, dlo.x, sq4.x); o0.y = fmaf(-2.f, dlo.y, sq4.y);
            o0.z = fmaf(-2.f, dlo.z, sq4.z); o0.w = fmaf(-2.f, dlo.w, sq4.w);
            o1.x = fmaf(-2.f, dhi.x, sq4.x); o1.y = fmaf(-2.f, dhi.y, sq4.y);
            o1.z = fmaf(-2.f, dhi.z, sq4.z); o1.w = fmaf(-2.f, dhi.w, sq4.w);
            *(float4*)(key + (2*p    )*NP + j0) = o0;
            *(float4*)(key + (2*p + 1)*NP + j0) = o1;
        }
    }
    __syncthreads();

    // ---- selection: warp w handles row w
    const int w = tid >> 5, L = tid & 31;
    float* krow = key + w*NP;
    float cm0 = FINF, cm1 = FINF;
    {
        const float4* c4 = (const float4*)(krow + L*32);
        const float4* d4 = (const float4*)(krow + (L + 32)*32);
        #pragma unroll
        for (int t = 0; t < 8; ++t){
            int tt = (t + L) & 7;
            float4 u = c4[tt];
            cm0 = fminf(cm0, fminf(fminf(u.x, u.y), fminf(u.z, u.w)));
            float4 v = d4[tt];
            cm1 = fminf(cm1, fminf(fminf(v.x, v.y), fminf(v.z, v.w)));
        }
    }
    int* knnp = g_knn + (b*NP + i0 + w)*KNN;
    for (int it = 0; it < KNN; ++it){
        float m = fminf(cm0, cm1);
        #pragma unroll
        for (int off = 16; off; off >>= 1)
            m = fminf(m, __shfl_xor_sync(0xffffffffu, m, off));
        unsigned e0 = __ballot_sync(0xffffffffu, cm0 == m);
        unsigned e1 = __ballot_sync(0xffffffffu, cm1 == m);
        int ch = e0 ? (__ffs(e0) - 1) : (32 + __ffs(e1) - 1);
        float v = krow[ch*32 + L];
        unsigned eq = __ballot_sync(0xffffffffu, v == m);
        int jl = __ffs(eq) - 1;
        int j = ch*32 + jl;
        if (L == jl){ krow[j] = FINF; v = FINF; }
        if (L == 0) knnp[it] = j;
        float nm = v;
        #pragma unroll
        for (int off = 16; off; off >>= 1)
            nm = fminf(nm, __shfl_xor_sync(0xffffffffu, nm, off));
        if (L == (ch & 31)){
            if (ch < 32) cm0 = nm; else cm1 = nm;
        }
    }
}

// ---------------- W transpose: W[o][half*CIN+c] -> WT[c][half*COUT+o] -----
__global__ void k_wt(const float* __restrict__ W, int CIN, int COUT){
    int idx = blockIdx.x*256 + threadIdx.x;
    int tot = 2*CIN*COUT;
    if (idx >= tot) return;
    int c = idx % CIN; int rest = idx / CIN;
    int o = rest % COUT; int half = rest / COUT;
    g_WT[c*(2*COUT) + half*COUT + o] = W[o*2*CIN + half*CIN + c];
}

// ---------------- tiled projection GEMM: [32 pts] x [2*COUT] x CIN --------
template<int CIN, int COUT>
__global__ __launch_bounds__(256) void k_proj2(){
    constexpr int OD = 2*COUT;          // 128 or 256
    constexpr int NG = 256/OD;          // groups (2 or 1)
    constexpr int PT = 32/NG;           // points per thread (16 or 32)
    constexpr int CCH = 16;
    __shared__ __align__(16) float ptsT[CIN*32];
    __shared__ __align__(16) float wt[CCH*OD];
    int pbase = blockIdx.x * 32;
    int tid = threadIdx.x;
    int u = tid & (OD-1), g = tid / OD;

    for (int idx = tid; idx < 32*CIN; idx += 256){
        int p = idx / CIN, c = idx - p*CIN;
        ptsT[c*32 + p] = g_feat[(pbase + p)*CF + c];
    }

    ull acc[PT/2];
    #pragma unroll
    for (int t = 0; t < PT/2; t++) acc[t] = 0ull;

    for (int c0 = 0; c0 < CIN; c0 += CCH){
        __syncthreads();
        for (int idx = tid; idx < CCH*OD; idx += 256){
            int cc = idx / OD;
            if (c0 + cc < CIN) wt[idx] = g_WT[(c0 + cc)*OD + (idx & (OD-1))];
        }
        __syncthreads();
        int cend = (CIN - c0 < CCH) ? (CIN - c0) : CCH;
        for (int cc = 0; cc < cend; ++cc){
            float w = wt[cc*OD + u];
            ull wp = pack2(w, w);
            const ull* pp = (const ull*)(ptsT + (c0 + cc)*32) + g*(PT/2);
            #pragma unroll
            for (int t = 0; t < PT/2; ++t) fma2(acc[t], wp, pp[t]);
        }
    }

    int o = (u < COUT) ? u : (u - COUT);
    float* dst = (u < COUT) ? g_A : g_B2;
    #pragma unroll
    for (int t = 0; t < PT/2; ++t){
        float v0, v1; unpack2(acc[t], v0, v1);
        int p = pbase + g*PT + 2*t;
        dst[(p    )*COUT + o] = v0;
        dst[(p + 1)*COUT + o] = v1;
    }
}

// ---------------- gather neighbors + affine + leaky + max over k ----------
template<int COUT>
__global__ void k_edge_max(const float* __restrict__ sv, const float* __restrict__ bv,
                           int offout){
    __shared__ int idxs[4*KNN];
    int P0 = blockIdx.x*4;
    int t = threadIdx.x;
    if (t < 4*KNN) idxs[t] = g_knn[P0*KNN + t];
    __syncthreads();
    int p = t / COUT, o = t - p*COUT;
    int P = P0 + p;
    int b = P >> 11, n = P & (NP-1);
    float Ai = g_A[P*COUT + o];
    float Bi = g_B2[P*COUT + o];
    float base = Bi - Ai;
    float hmax = -3.4e38f, hmin = 3.4e38f;
    const int* ip = idxs + p*KNN;
    #pragma unroll
    for (int k = 0; k < KNN; k++){
        float v = g_A[(b*NP + ip[k])*COUT + o] + base;
        hmax = fmaxf(hmax, v); hmin = fminf(hmin, v);
    }
    float s = sv[o], bb = bv[o];
    float y = fmaxf(lrelu(fmaf(s, hmax, bb)), lrelu(fmaf(s, hmin, bb)));
    g_feat[P*CF + offout + o] = y;
    g_featT[(b*CF + offout + o)*NP + n] = y;
}

// ---------------- W5 transpose for coalesced loads ------------------------
__global__ void k_w5t(const float* __restrict__ W5){
    int idx = blockIdx.x*256 + threadIdx.x;
    if (idx < 1024*323){
        int o = idx / 323, c = idx - o*323;
        g_W5T[c*1024 + o] = W5[idx];
    }
}

// ---------------- global 1024-ch conv + max-pool over N -------------------
// Block: 32 points x 256 outs. Thread = 4 outs x 8 points (smem:fma = 1:1).
__global__ __launch_bounds__(256) void k_glob(const float* __restrict__ s5,
                                              const float* __restrict__ b5){
    __shared__ __align__(16) float cfT[CF*32];    // [c][p], 41.3 KB
    int b = blockIdx.z;
    int p0 = blockIdx.x*32;
    for (int idx = threadIdx.x; idx < 32*CF; idx += 256){
        int p = idx / CF, c = idx - p*CF;
        cfT[c*32 + p] = g_feat[(b*NP + p0 + p)*CF + c];
    }
    __syncthreads();
    int og = threadIdx.x & 63;          // out-group -> 4 consecutive outs
    int pg = threadIdx.x >> 6;          // point-group -> 8 points
    int o = blockIdx.y*256 + og*4;
    ull acc[4][4];                      // [out][point-pair]
    #pragma unroll
    for (int k = 0; k < 4; k++)
        #pragma unroll
        for (int q = 0; q < 4; q++) acc[k][q] = 0ull;
    #pragma unroll 2
    for (int c = 0; c < CF; ++c){
        float4 wv = __ldg((const float4*)(g_W5T + c*1024 + o));
        ull w0 = pack2(wv.x, wv.x), w1 = pack2(wv.y, wv.y);
        ull w2 = pack2(wv.z, wv.z), w3 = pack2(wv.w, wv.w);
        const ull* pp = (const ull*)(cfT + c*32) + pg*4;
        ull u0 = pp[0], u1 = pp[1], u2 = pp[2], u3 = pp[3];
        fma2(acc[0][0], w0, u0); fma2(acc[0][1], w0, u1);
        fma2(acc[0][2], w0, u2); fma2(acc[0][3], w0, u3);
        fma2(acc[1][0], w1, u0); fma2(acc[1][1], w1, u1);
        fma2(acc[1][2], w1, u2); fma2(acc[1][3], w1, u3);
        fma2(acc[2][0], w2, u0); fma2(acc[2][1], w2, u1);
        fma2(acc[2][2], w2, u2); fma2(acc[2][3], w2, u3);
        fma2(acc[3][0], w3, u0); fma2(acc[3][1], w3, u1);
        fma2(acc[3][2], w3, u2); fma2(acc[3][3], w3, u3);
    }
    #pragma unroll
    for (int k = 0; k < 4; ++k){
        float hmax = -3.4e38f, hmin = 3.4e38f;
        #pragma unroll
        for (int q = 0; q < 4; ++q){
            float x0, x1; unpack2(acc[k][q], x0, x1);
            hmax = fmaxf(hmax, fmaxf(x0, x1));
            hmin = fminf(hmin, fminf(x0, x1));
        }
        float s = s5[o + k], bb = b5[o + k];
        float y = fmaxf(lrelu(fmaf(s, hmax, bb)), lrelu(fmaf(s, hmin, bb)));
        atomicMax(&g_gmax[b*1024 + o + k], enc_f(y));
    }
}

// ---------------- decode maxpool, emit gfeat ------------------------------
__global__ void k_finalize(float* __restrict__ out){
    int i = blockIdx.x*256 + threadIdx.x;        // NB*1024 threads
    float f = dec_f(g_gmax[i]);
    g_gfeat[i] = f;
    out[NB*40 + i] = f;                           // gfeat after logits
}

// ---------------- FC head: warp per output, coalesced float4 W reads ------
template<int INDIM>
__global__ void k_fcw(const float* __restrict__ W, const float* __restrict__ bias,
                      const float* __restrict__ sv, const float* __restrict__ Bv,
                      float* __restrict__ dout, int outdim, int layer){
    int b = blockIdx.x;
    int o = blockIdx.y*8 + (threadIdx.x >> 5);
    int L = threadIdx.x & 31;
    if (o >= outdim) return;
    const float* in = (layer == 1) ? (g_gfeat + b*1024)
                    : (layer == 2) ? (g_h1 + b*512) : (g_h2 + b*256);
    float* outp = (layer == 1) ? (g_h1 + b*512)
                : (layer == 2) ? (g_h2 + b*256) : (dout + b*40);
    const float4* Wr = (const float4*)(W + o*INDIM);
    const float4* vr = (const float4*)in;
    float a = 0.f;
    #pragma unroll
    for (int t = 0; t < INDIM/128; ++t){
        float4 w = __ldg(Wr + t*32 + L);
        float4 v = __ldg(vr + t*32 + L);
        a = fmaf(w.x, v.x, fmaf(w.y, v.y, fmaf(w.z, v.z, fmaf(w.w, v.w, a))));
    }
    #pragma unroll
    for (int off = 16; off; off >>= 1)
        a += __shfl_xor_sync(0xffffffffu, a, off);
    if (L == 0){
        a += bias[o];
        if (layer != 3) a = lrelu(fmaf(a, sv[o], Bv[o]));
        outp[o] = a;
    }
}

// ---------------- launch --------------------------------------------------
extern "C" void kernel_launch(void* const* d_in, const int* in_sizes, int n_in,
                              void* d_out, int out_size){
    const float* x   = (const float*)d_in[0];
    const float* W1  = (const float*)d_in[1];
    const float* s1  = (const float*)d_in[2];
    const float* b1  = (const float*)d_in[3];
    const float* W2  = (const float*)d_in[4];
    const float* s2  = (const float*)d_in[5];
    const float* b2  = (const float*)d_in[6];
    const float* W3  = (const float*)d_in[7];
    const float* s3  = (const float*)d_in[8];
    const float* b3  = (const float*)d_in[9];
    const float* W4  = (const float*)d_in[10];
    const float* s4  = (const float*)d_in[11];
    const float* b4  = (const float*)d_in[12];
    const float* W5  = (const float*)d_in[13];
    const float* s5  = (const float*)d_in[14];
    const float* b5  = (const float*)d_in[15];
    const float* fW1 = (const float*)d_in[16];
    const float* fb1 = (const float*)d_in[17];
    const float* fs1 = (const float*)d_in[18];
    const float* fB1 = (const float*)d_in[19];
    const float* fW2 = (const float*)d_in[20];
    const float* fb2 = (const float*)d_in[21];
    const float* fs2 = (const float*)d_in[22];
    const float* fB2 = (const float*)d_in[23];
    const float* fW3 = (const float*)d_in[24];
    const float* fb3 = (const float*)d_in[25];
    float* out = (float*)d_out;

    const int sm1 = (8*NP + 8*3 ) * 4;
    const int sm2 = (8*NP + 8*67) * 4;
    const int smB = (8*NP + 8*64) * 4;
    cudaFuncSetAttribute((const void*)k_dist_topk<0,3,true,false>,
                         cudaFuncAttributeMaxDynamicSharedMemorySize, sm1);
    cudaFuncSetAttribute((const void*)k_dist_topk<0,67,true,true>,
                         cudaFuncAttributeMaxDynamicSharedMemorySize, sm2);
    cudaFuncSetAttribute((const void*)k_dist_topk<67,131,false,true>,
                         cudaFuncAttributeMaxDynamicSharedMemorySize, smB);
    cudaFuncSetAttribute((const void*)k_dist_topk<131,195,false,false>,
                         cudaFuncAttributeMaxDynamicSharedMemorySize, smB);

    k_init<<<NB*NP/256, 256>>>(x);
    k_initmax<<<(NB*1024 + 255)/256, 256>>>();

    // ---- EdgeConv stage 1: Cin=3, Cout=64, out offset 3
    k_sq_add<<<NB*NP/256, 256>>>(0, 3, 1);
    k_dist_topk<0,3,true,false><<<dim3(NP/8, NB), 256, sm1>>>();
    k_wt<<<(2*3*64 + 255)/256, 256>>>(W1, 3, 64);
    k_proj2<3,64><<<NB*NP/32, 256>>>();
    k_edge_max<64><<<NB*NP/4, 256>>>(s1, b1, 3);

    // ---- EdgeConv stage 2: Cin=67, Cout=64, out offset 67
    k_sq_add<<<NB*NP/256, 256>>>(3, 67, 0);
    k_dist_topk<0,67,true,true><<<dim3(NP/8, NB), 256, sm2>>>();
    k_wt<<<(2*67*64 + 255)/256, 256>>>(W2, 67, 64);
    k_proj2<67,64><<<NB*NP/32, 256>>>();
    k_edge_max<64><<<NB*NP/4, 256>>>(s2, b2, 67);

    // ---- EdgeConv stage 3: Cin=131, Cout=64, out offset 131
    k_sq_add<<<NB*NP/256, 256>>>(67, 131, 0);
    k_dist_topk<67,131,false,true><<<dim3(NP/8, NB), 256, smB>>>();
    k_wt<<<(2*131*64 + 255)/256, 256>>>(W3, 131, 64);
    k_proj2<131,64><<<NB*NP/32, 256>>>();
    k_edge_max<64><<<NB*NP/4, 256>>>(s3, b3, 131);

    // ---- EdgeConv stage 4: Cin=195, Cout=128, out offset 195
    k_sq_add<<<NB*NP/256, 256>>>(131, 195, 0);
    k_dist_topk<131,195,false,false><<<dim3(NP/8, NB), 256, smB>>>();
    k_wt<<<(2*195*128 + 255)/256, 256>>>(W4, 195, 128);
    k_proj2<195,128><<<NB*NP/32, 256>>>();
    k_edge_max<128><<<NB*NP/4, 512>>>(s4, b4, 195);

    // ---- Global conv (1024) + maxpool over N
    k_w5t<<<(1024*323 + 255)/256, 256>>>(W5);
    k_glob<<<dim3(NP/32, 4, NB), 256>>>(s5, b5);
    k_finalize<<<NB*1024/256, 256>>>(out);

    // ---- FC head (warp per output)
    k_fcw<1024><<<dim3(NB, 64), 256>>>(fW1, fb1, fs1, fB1, out, 512, 1);
    k_fcw< 512><<<dim3(NB, 32), 256>>>(fW2, fb2, fs2, fB2, out, 256, 2);
    k_fcw< 256><<<dim3(NB,  5), 256>>>(fW3, fb3, fs2, fB2, out,  40, 3);
}